// round 6
// baseline (speedup 1.0000x reference)
#include <cuda_runtime.h>
#include <cstdint>

// Problem constants
#define NP 21504   // priors per image
#define HALF 10752 // NP/2
#define KC 1024    // top-k
#define BB 64      // batch
#define NT 512     // threads per block
#define WORDS 32   // KC/32 mask words
#define CCAP 2048  // candidate buffer (>= KC + bin slack)
#define PAD 33
#define SLICES 4   // supmat blocks per image
#define WPS 8      // words per slice
#define NBIN 4096  // 14-bit score histogram

// ---------------- global scratch (device globals: no allocs) ----------------
__device__ float              g_scores[BB * NP];             // 5.5 MB
__device__ unsigned int       g_hist[BB * 2 * NBIN];         // 2 MB
__device__ unsigned long long g_keys[BB * KC];
__device__ float              g_bx1[BB * KC];
__device__ float              g_by1[BB * KC];
__device__ float              g_bx2[BB * KC];
__device__ float              g_by2[BB * KC];
__device__ float              g_bar[BB * KC];
__device__ unsigned int       g_sup[BB * WORDS * KC];        // w-major per image
__device__ unsigned int       g_rowany[BB * SLICES * 32];

// ===================== k1: softmax + 14-bit histogram (128 blocks) ==========
__global__ __launch_bounds__(NT)
void k1_score(const float* __restrict__ confs)
{
    __shared__ unsigned int s_hist[NBIN];
    const int b    = blockIdx.y;
    const int half = blockIdx.x;
    const int tid  = threadIdx.x;
    const int lane = tid & 31;
    const unsigned FULL = 0xffffffffu;

    for (int i = tid; i < NBIN; i += NT) s_hist[i] = 0;
    __syncthreads();

    const float* conf = confs + (size_t)b * NP * 2;
    const int n0 = half * HALF;
    for (int n = n0 + tid; n < n0 + HALF; n += NT) {
        float2 c = __ldg((const float2*)(conf + 2 * n));
        // XLA softmax: m=max, e0=exp(x-m), e1=exp(y-m), s=e1/(e0+e1).
        // One of the exps is exp(0)=1 exactly -> single expf, bit-identical.
        float s;
        if (c.y >= c.x) {
            float e0 = expf(__fsub_rn(c.x, c.y));
            s = __fdiv_rn(1.0f, __fadd_rn(e0, 1.0f));
        } else {
            float e1 = expf(__fsub_rn(c.y, c.x));
            s = __fdiv_rn(e1, __fadd_rn(1.0f, e1));
        }
        g_scores[(size_t)b * NP + n] = s;
        unsigned int digit = __float_as_uint(s) >> 18;   // < 4096 (s < 1)
        unsigned int mmask = __match_any_sync(FULL, digit);
        if (lane == (__ffs(mmask) - 1))
            atomicAdd(&s_hist[digit], __popc(mmask));
    }
    __syncthreads();
    for (int i = tid; i < NBIN; i += NT)
        g_hist[((b * 2 + half) << 12) + i] = s_hist[i];
}

// ===================== kA2: threshold + collect + sort + decode =============
__global__ __launch_bounds__(NT, 1)
void kA2_select(const float* __restrict__ locs,
                const float* __restrict__ priors)
{
    __shared__ unsigned int       s_hist[NBIN];     // 16 KB
    __shared__ unsigned long long s_keys[CCAP];     // 16 KB
    __shared__ unsigned int       s_wsum[16];
    __shared__ int                s_misc[4];

    const int b    = blockIdx.x;
    const int tid  = threadIdx.x;
    const int lane = tid & 31;
    const int wid  = tid >> 5;
    const unsigned FULL = 0xffffffffu;

    // sum the two half-image histograms
    for (int i = tid; i < NBIN; i += NT)
        s_hist[i] = g_hist[((b * 2) << 12) + i] +
                    g_hist[((b * 2 + 1) << 12) + i];
    if (tid == 0) s_misc[0] = 0;
    __syncthreads();

    // hierarchical suffix scan over 4096 bins: 8 bins/thread
    {
        unsigned int v[8], S = 0;
        #pragma unroll
        for (int k = 0; k < 8; k++) { v[k] = s_hist[8 * tid + k]; S += v[k]; }
        unsigned int sfx = S;
        #pragma unroll
        for (int off = 1; off < 32; off <<= 1) {
            unsigned int u = __shfl_down_sync(FULL, sfx, off);
            if (lane + off < 32) sfx += u;
        }
        if (lane == 0) s_wsum[wid] = sfx;   // warp total
        __syncthreads();
        unsigned int cross = 0;
        for (int w2 = wid + 1; w2 < 16; w2++) cross += s_wsum[w2];
        unsigned int T_t = sfx + cross;     // suffix over threads >= tid
        unsigned int sb[9];
        sb[8] = T_t - S;                    // suffix(8*tid + 8)
        #pragma unroll
        for (int k = 7; k >= 0; k--) sb[k] = sb[k + 1] + v[k];
        #pragma unroll
        for (int k = 0; k < 8; k++)
            if (sb[k] >= (unsigned)KC && sb[k + 1] < (unsigned)KC)
                s_misc[1] = 8 * tid + k;    // exactly one thread writes
    }
    for (int i = tid; i < CCAP; i += NT) s_keys[i] = 0ULL;
    __syncthreads();

    const unsigned int Tb = (unsigned int)s_misc[1] << 18;  // bin lower edge

    // collect all scores >= Tb (superset of top-K), warp-aggregated
    const float* sc = g_scores + (size_t)b * NP;
    for (int n = tid; n < NP; n += NT) {
        unsigned int sbits = __float_as_uint(sc[n]);
        bool c = (sbits >= Tb);
        unsigned int bal = __ballot_sync(FULL, c);
        if (bal) {
            int leader = __ffs(bal) - 1;
            int base = 0;
            if (lane == leader) base = atomicAdd(&s_misc[0], __popc(bal));
            base = __shfl_sync(FULL, base, leader);
            if (c) {
                int p = base + __popc(bal & ((1u << lane) - 1u));
                if (p < CCAP)
                    s_keys[p] = ((unsigned long long)sbits << 32) |
                                (unsigned int)(~n);
            }
        }
    }
    __syncthreads();

    // bitonic sort 2048 keys descending
    for (int k = 2; k <= CCAP; k <<= 1) {
        for (int j = k >> 1; j > 0; j >>= 1) {
            for (int i = tid; i < CCAP; i += NT) {
                int ixj = i ^ j;
                if (ixj > i) {
                    unsigned long long a = s_keys[i];
                    unsigned long long c = s_keys[ixj];
                    bool desc = ((i & k) == 0);
                    if (desc ? (a < c) : (a > c)) {
                        s_keys[i] = c; s_keys[ixj] = a;
                    }
                }
            }
            __syncthreads();
        }
    }

    // decode boxes (no FMA contraction) + write scratch
    const float* loc = locs + (size_t)b * NP * 4;
    for (int t = tid; t < KC; t += NT) {
        unsigned long long key = s_keys[t];
        int idx = (int)(~(unsigned int)key);
        float4 l = __ldg((const float4*)(loc + 4 * (size_t)idx));
        float4 p = __ldg((const float4*)(priors + 4 * (size_t)idx));
        float cx = __fadd_rn(p.x, __fmul_rn(__fmul_rn(l.x, 0.1f), p.z));
        float cy = __fadd_rn(p.y, __fmul_rn(__fmul_rn(l.y, 0.1f), p.w));
        float w  = __fmul_rn(p.z, expf(__fmul_rn(l.z, 0.2f)));
        float h  = __fmul_rn(p.w, expf(__fmul_rn(l.w, 0.2f)));
        float x1 = __fsub_rn(cx, __fdiv_rn(w, 2.0f));
        float y1 = __fsub_rn(cy, __fdiv_rn(h, 2.0f));
        float x2 = __fadd_rn(x1, w);
        float y2 = __fadd_rn(y1, h);
        size_t o = (size_t)b * KC + t;
        g_bx1[o] = x1; g_by1[o] = y1; g_bx2[o] = x2; g_by2[o] = y2;
        float aw = fmaxf(__fsub_rn(x2, x1), 0.0f);
        float ah = fmaxf(__fsub_rn(y2, y1), 0.0f);
        g_bar[o] = __fmul_rn(aw, ah);
        g_keys[o] = key;
    }
}

// ===================== kS: suppression bitmatrix (4 slices/image) ============
#define IOU_HI 0.400008f
#define IOU_LO 0.399992f

__global__ __launch_bounds__(NT)
void kS_supmat()
{
    __shared__ float s_x1[KC], s_y1[KC], s_x2[KC], s_y2[KC], s_area[KC];
    __shared__ unsigned char s_rowf[KC];

    const int b     = blockIdx.y;
    const int slice = blockIdx.x;
    const int tid   = threadIdx.x;
    const int lane  = tid & 31;

    for (int t = tid; t < KC; t += NT) {
        size_t o = (size_t)b * KC + t;
        s_x1[t] = g_bx1[o]; s_y1[t] = g_by1[o];
        s_x2[t] = g_bx2[o]; s_y2[t] = g_by2[o];
        s_area[t] = g_bar[o];
        s_rowf[t] = 0;
    }
    __syncthreads();

    unsigned int* supb = g_sup + (size_t)b * WORDS * KC;
    for (int t = tid; t < WPS * KC; t += NT) {
        int w  = slice * WPS + (t >> 10);  // warp-uniform
        int i  = t & 1023;                 // consecutive across lanes
        int j0 = w << 5;
        int ibase = i & ~31;               // warp-uniform
        unsigned int m = 0;
        float xi1 = s_x1[i], yi1 = s_y1[i];
        float xi2 = s_x2[i], yi2 = s_y2[i];
        float ai  = s_area[i];
        if (j0 >= ibase + 32) {
            // full word: all j > i for every lane -> no per-lane check
            #pragma unroll 4
            for (int jj = 0; jj < 32; jj++) {
                int j = j0 + jj;
                float lx = fmaxf(xi1, s_x1[j]);
                float ly = fmaxf(yi1, s_y1[j]);
                float rx = fminf(xi2, s_x2[j]);
                float ry = fminf(yi2, s_y2[j]);
                float ww = fmaxf(__fsub_rn(rx, lx), 0.0f);
                float hh = fmaxf(__fsub_rn(ry, ly), 0.0f);
                float inter = __fmul_rn(ww, hh);
                float um = __fsub_rn(__fadd_rn(ai, s_area[j]), inter);
                bool hi = inter > __fmul_rn(IOU_HI, um);
                bool lo = inter < __fmul_rn(IOU_LO, um);
                bool sup = hi;
                if (!hi && !lo)
                    sup = (__fdiv_rn(inter, fmaxf(um, 1e-9f)) > 0.4f);
                if (sup) m |= (1u << jj);
            }
        } else if (j0 + 31 > i) {
            // diagonal word
            #pragma unroll 4
            for (int jj = 0; jj < 32; jj++) {
                int j = j0 + jj;
                if (j <= i) continue;
                float lx = fmaxf(xi1, s_x1[j]);
                float ly = fmaxf(yi1, s_y1[j]);
                float rx = fminf(xi2, s_x2[j]);
                float ry = fminf(yi2, s_y2[j]);
                float ww = fmaxf(__fsub_rn(rx, lx), 0.0f);
                float hh = fmaxf(__fsub_rn(ry, ly), 0.0f);
                float inter = __fmul_rn(ww, hh);
                float um = __fsub_rn(__fadd_rn(ai, s_area[j]), inter);
                bool hi = inter > __fmul_rn(IOU_HI, um);
                bool lo = inter < __fmul_rn(IOU_LO, um);
                bool sup = hi;
                if (!hi && !lo)
                    sup = (__fdiv_rn(inter, fmaxf(um, 1e-9f)) > 0.4f);
                if (sup) m |= (1u << jj);
            }
        }
        supb[(w << 10) + i] = m;           // coalesced across lanes
        if (m) s_rowf[i] = 1;              // benign race (writes of 1)
    }
    __syncthreads();
    for (int r = tid; r < KC; r += NT) {
        unsigned int bal = __ballot_sync(0xffffffffu, s_rowf[r] != 0);
        if (lane == 0)
            g_rowany[((b * SLICES + slice) << 5) + (r >> 5)] = bal;
    }
}

// ===================== kB: stage + greedy scan + output ======================
#define KB_SUP    0                       // 1024*33*4 = 135168
#define KB_X1     135168
#define KB_Y1     139264
#define KB_X2     143360
#define KB_Y2     147456
#define KB_SC     151552
#define KB_RAW    155648                  // u32[32]
#define KB_VALW   155776                  // u32[32]
#define KB_KEEPW  155904                  // u32[32]
#define KB_TOTAL  156032

__global__ __launch_bounds__(NT, 1)
void kB_scan(float* __restrict__ out, int out_size)
{
    extern __shared__ unsigned char sm[];
    unsigned int*  s_sup   = (unsigned int*)(sm + KB_SUP);
    float*         s_x1    = (float*)(sm + KB_X1);
    float*         s_y1    = (float*)(sm + KB_Y1);
    float*         s_x2    = (float*)(sm + KB_X2);
    float*         s_y2    = (float*)(sm + KB_Y2);
    float*         s_sc    = (float*)(sm + KB_SC);
    unsigned int*  s_raw   = (unsigned int*)(sm + KB_RAW);
    unsigned int*  s_validw= (unsigned int*)(sm + KB_VALW);
    unsigned int*  s_keepw = (unsigned int*)(sm + KB_KEEPW);

    const int b    = blockIdx.x;
    const int tid  = threadIdx.x;
    const int lane = tid & 31;
    const unsigned FULL = 0xffffffffu;

    // validity + rowany first (so staging can be filtered)
    for (int t = tid; t < KC; t += NT) {
        size_t o = (size_t)b * KC + t;
        s_x1[t] = g_bx1[o]; s_y1[t] = g_by1[o];
        s_x2[t] = g_bx2[o]; s_y2[t] = g_by2[o];
        float sc = __uint_as_float((unsigned int)(g_keys[o] >> 32));
        s_sc[t] = sc;
        unsigned int bal = __ballot_sync(FULL, sc > 0.5f);
        if (lane == 0) s_validw[t >> 5] = bal;
    }
    if (tid < 32) {
        unsigned int ra = 0;
        #pragma unroll
        for (int sl = 0; sl < SLICES; sl++)
            ra |= g_rowany[((b * SLICES + sl) << 5) + tid];
        s_raw[tid] = ra;
    }
    __syncthreads();

    // stage only rows that can be kept suppressors (valid & rowany)
    const unsigned int* supb = g_sup + (size_t)b * WORDS * KC;
    for (int t = tid; t < WORDS * KC; t += NT) {
        int w = t >> 10;                       // warp-uniform
        int i = t & 1023;                      // consecutive across lanes
        unsigned int need = (s_raw[i >> 5] & s_validw[i >> 5]) >> (i & 31);
        if (need & 1u)
            s_sup[i * PAD + w] = supb[t];
    }
    __syncthreads();

    // greedy scan: one warp, suppressors-only loop, no shfl in chain
    if (tid < 32) {
        unsigned int remv = 0;   // lane holds removed-mask word `lane`
        for (int w = 0; w < 32; w++) {
            unsigned int rm = __shfl_sync(FULL, remv, w);  // once per word
            unsigned int vw = s_validw[w];
            unsigned int ra = s_raw[w];
            unsigned int kw = 0;
            unsigned int pending = vw & ra;
            unsigned int scand;
            while ((scand = pending & ~rm) != 0) {
                int bit = __ffs(scand) - 1;
                pending &= ~(1u << bit);
                kw |= (1u << bit);
                int i = (w << 5) + bit;
                unsigned int rowl = s_sup[i * PAD + lane];  // per-lane word
                unsigned int roww = s_sup[i * PAD + w];     // broadcast
                remv |= rowl;
                rm   |= roww;
            }
            kw |= vw & ~ra & ~rm;  // non-suppressors kept iff never removed
            if (lane == 0) s_keepw[w] = kw;
        }
    }
    __syncthreads();

    // outputs: dets [B,KC,5], keep [B,KC]
    const bool write_keep = (out_size >= BB * KC * 6);
    for (int t = tid; t < KC; t += NT) {
        bool kept = (s_keepw[t >> 5] >> (t & 31)) & 1u;
        float kf = kept ? 1.0f : 0.0f;
        size_t base = ((size_t)b * KC + t) * 5;
        out[base + 0] = __fmul_rn(s_x1[t], kf);
        out[base + 1] = __fmul_rn(s_y1[t], kf);
        out[base + 2] = __fmul_rn(s_x2[t], kf);
        out[base + 3] = __fmul_rn(s_y2[t], kf);
        out[base + 4] = __fmul_rn(s_sc[t], kf);
        if (write_keep)
            out[(size_t)BB * KC * 5 + (size_t)b * KC + t] = kf;
    }
}

// ======================= launch ==============================================
extern "C" void kernel_launch(void* const* d_in, const int* in_sizes, int n_in,
                              void* d_out, int out_size)
{
    (void)in_sizes; (void)n_in;
    cudaFuncSetAttribute(kB_scan,
        cudaFuncAttributeMaxDynamicSharedMemorySize, KB_TOTAL);
    const float* locs   = (const float*)d_in[0];
    const float* confs  = (const float*)d_in[1];
    const float* priors = (const float*)d_in[2];
    float* out = (float*)d_out;

    k1_score<<<dim3(2, BB), NT>>>(confs);
    kA2_select<<<BB, NT>>>(locs, priors);
    kS_supmat<<<dim3(SLICES, BB), NT>>>();
    kB_scan<<<BB, NT, KB_TOTAL>>>(out, out_size);
}

// round 7
// speedup vs baseline: 1.0030x; 1.0030x over previous
#include <cuda_runtime.h>
#include <cstdint>

// Problem constants
#define NP 21504   // priors per image
#define HALF 10752 // NP/2
#define KC 1024    // top-k
#define BB 64      // batch
#define NT 512     // threads per block
#define WORDS 32   // KC/32 mask words
#define CCAP 2048  // candidate buffer (>= KC + bin slack)
#define PAD 33
#define SLICES 4   // supmat blocks per image
#define WPS 8      // words per slice
#define NBIN 4096  // 14-bit score histogram

// ---------------- global scratch (device globals: no allocs) ----------------
__device__ float              g_scores[BB * NP];             // 5.5 MB
__device__ unsigned int       g_hist[BB * 2 * NBIN];         // 2 MB
__device__ unsigned long long g_keys[BB * KC];
__device__ float              g_bx1[BB * KC];
__device__ float              g_by1[BB * KC];
__device__ float              g_bx2[BB * KC];
__device__ float              g_by2[BB * KC];
__device__ float              g_bar[BB * KC];
__device__ unsigned int       g_sup[BB * WORDS * KC];        // w-major per image
__device__ unsigned int       g_rowany[BB * SLICES * 32];

// ===================== k1: softmax + 14-bit histogram (128 blocks) ==========
__global__ __launch_bounds__(NT)
void k1_score(const float* __restrict__ confs)
{
    __shared__ unsigned int s_hist[NBIN];
    const int b    = blockIdx.y;
    const int half = blockIdx.x;
    const int tid  = threadIdx.x;
    const int lane = tid & 31;
    const unsigned FULL = 0xffffffffu;

    for (int i = tid; i < NBIN; i += NT) s_hist[i] = 0;
    __syncthreads();

    const float* conf = confs + (size_t)b * NP * 2;
    const int n0 = half * HALF;
    for (int n = n0 + tid; n < n0 + HALF; n += NT) {
        float2 c = __ldg((const float2*)(conf + 2 * n));
        // XLA softmax: one exp is exp(0)=1 exactly -> single expf, bit-identical
        float s;
        if (c.y >= c.x) {
            float e0 = expf(__fsub_rn(c.x, c.y));
            s = __fdiv_rn(1.0f, __fadd_rn(e0, 1.0f));
        } else {
            float e1 = expf(__fsub_rn(c.y, c.x));
            s = __fdiv_rn(e1, __fadd_rn(1.0f, e1));
        }
        g_scores[(size_t)b * NP + n] = s;
        unsigned int digit = __float_as_uint(s) >> 18;   // < 4096 (s < 1)
        unsigned int mmask = __match_any_sync(FULL, digit);
        if (lane == (__ffs(mmask) - 1))
            atomicAdd(&s_hist[digit], __popc(mmask));
    }
    __syncthreads();
    for (int i = tid; i < NBIN; i += NT)
        g_hist[((b * 2 + half) << 12) + i] = s_hist[i];
}

// ===================== kA2: threshold + collect + sort + decode =============
__global__ __launch_bounds__(NT, 1)
void kA2_select(const float* __restrict__ locs,
                const float* __restrict__ priors)
{
    __shared__ unsigned int       s_hist[NBIN];     // 16 KB
    __shared__ unsigned long long s_keys[CCAP];     // 16 KB
    __shared__ unsigned int       s_wsum[16];
    __shared__ int                s_misc[4];

    const int b    = blockIdx.x;
    const int tid  = threadIdx.x;
    const int lane = tid & 31;
    const int wid  = tid >> 5;
    const unsigned FULL = 0xffffffffu;

    for (int i = tid; i < NBIN; i += NT)
        s_hist[i] = g_hist[((b * 2) << 12) + i] +
                    g_hist[((b * 2 + 1) << 12) + i];
    if (tid == 0) s_misc[0] = 0;
    __syncthreads();

    // hierarchical suffix scan over 4096 bins: 8 bins/thread
    {
        unsigned int v[8], S = 0;
        #pragma unroll
        for (int k = 0; k < 8; k++) { v[k] = s_hist[8 * tid + k]; S += v[k]; }
        unsigned int sfx = S;
        #pragma unroll
        for (int off = 1; off < 32; off <<= 1) {
            unsigned int u = __shfl_down_sync(FULL, sfx, off);
            if (lane + off < 32) sfx += u;
        }
        if (lane == 0) s_wsum[wid] = sfx;
        __syncthreads();
        unsigned int cross = 0;
        for (int w2 = wid + 1; w2 < 16; w2++) cross += s_wsum[w2];
        unsigned int T_t = sfx + cross;
        unsigned int sb[9];
        sb[8] = T_t - S;
        #pragma unroll
        for (int k = 7; k >= 0; k--) sb[k] = sb[k + 1] + v[k];
        #pragma unroll
        for (int k = 0; k < 8; k++)
            if (sb[k] >= (unsigned)KC && sb[k + 1] < (unsigned)KC)
                s_misc[1] = 8 * tid + k;
    }
    for (int i = tid; i < CCAP; i += NT) s_keys[i] = 0ULL;
    __syncthreads();

    const unsigned int Tb = (unsigned int)s_misc[1] << 18;  // bin lower edge

    // collect all scores >= Tb (superset of top-K), warp-aggregated
    const float* sc = g_scores + (size_t)b * NP;
    for (int n = tid; n < NP; n += NT) {
        unsigned int sbits = __float_as_uint(sc[n]);
        bool c = (sbits >= Tb);
        unsigned int bal = __ballot_sync(FULL, c);
        if (bal) {
            int leader = __ffs(bal) - 1;
            int base = 0;
            if (lane == leader) base = atomicAdd(&s_misc[0], __popc(bal));
            base = __shfl_sync(FULL, base, leader);
            if (c) {
                int p = base + __popc(bal & ((1u << lane) - 1u));
                if (p < CCAP)
                    s_keys[p] = ((unsigned long long)sbits << 32) |
                                (unsigned int)(~n);
            }
        }
    }
    __syncthreads();

    // bitonic sort 2048 keys descending
    for (int k = 2; k <= CCAP; k <<= 1) {
        for (int j = k >> 1; j > 0; j >>= 1) {
            for (int i = tid; i < CCAP; i += NT) {
                int ixj = i ^ j;
                if (ixj > i) {
                    unsigned long long a = s_keys[i];
                    unsigned long long c = s_keys[ixj];
                    bool desc = ((i & k) == 0);
                    if (desc ? (a < c) : (a > c)) {
                        s_keys[i] = c; s_keys[ixj] = a;
                    }
                }
            }
            __syncthreads();
        }
    }

    // decode boxes (no FMA contraction) + write scratch
    const float* loc = locs + (size_t)b * NP * 4;
    for (int t = tid; t < KC; t += NT) {
        unsigned long long key = s_keys[t];
        int idx = (int)(~(unsigned int)key);
        float4 l = __ldg((const float4*)(loc + 4 * (size_t)idx));
        float4 p = __ldg((const float4*)(priors + 4 * (size_t)idx));
        float cx = __fadd_rn(p.x, __fmul_rn(__fmul_rn(l.x, 0.1f), p.z));
        float cy = __fadd_rn(p.y, __fmul_rn(__fmul_rn(l.y, 0.1f), p.w));
        float w  = __fmul_rn(p.z, expf(__fmul_rn(l.z, 0.2f)));
        float h  = __fmul_rn(p.w, expf(__fmul_rn(l.w, 0.2f)));
        float x1 = __fsub_rn(cx, __fdiv_rn(w, 2.0f));
        float y1 = __fsub_rn(cy, __fdiv_rn(h, 2.0f));
        float x2 = __fadd_rn(x1, w);
        float y2 = __fadd_rn(y1, h);
        size_t o = (size_t)b * KC + t;
        g_bx1[o] = x1; g_by1[o] = y1; g_bx2[o] = x2; g_by2[o] = y2;
        float aw = fmaxf(__fsub_rn(x2, x1), 0.0f);
        float ah = fmaxf(__fsub_rn(y2, y1), 0.0f);
        g_bar[o] = __fmul_rn(aw, ah);
        g_keys[o] = key;
    }
}

// ===================== kS: suppression bitmatrix (4 slices/image) ============
#define IOU_HI 0.400008f
#define IOU_LO 0.399992f

__global__ __launch_bounds__(NT)
void kS_supmat()
{
    __shared__ float s_x1[KC], s_y1[KC], s_x2[KC], s_y2[KC], s_area[KC];
    __shared__ unsigned char s_rowf[KC];

    const int b     = blockIdx.y;
    const int slice = blockIdx.x;
    const int tid   = threadIdx.x;
    const int lane  = tid & 31;

    for (int t = tid; t < KC; t += NT) {
        size_t o = (size_t)b * KC + t;
        s_x1[t] = g_bx1[o]; s_y1[t] = g_by1[o];
        s_x2[t] = g_bx2[o]; s_y2[t] = g_by2[o];
        s_area[t] = g_bar[o];
        s_rowf[t] = 0;
    }
    __syncthreads();

    unsigned int* supb = g_sup + (size_t)b * WORDS * KC;
    for (int t = tid; t < WPS * KC; t += NT) {
        int w  = slice * WPS + (t >> 10);
        int i  = t & 1023;
        int j0 = w << 5;
        int ibase = i & ~31;
        unsigned int m = 0;
        float xi1 = s_x1[i], yi1 = s_y1[i];
        float xi2 = s_x2[i], yi2 = s_y2[i];
        float ai  = s_area[i];
        if (j0 >= ibase + 32) {
            #pragma unroll 4
            for (int jj = 0; jj < 32; jj++) {
                int j = j0 + jj;
                float lx = fmaxf(xi1, s_x1[j]);
                float ly = fmaxf(yi1, s_y1[j]);
                float rx = fminf(xi2, s_x2[j]);
                float ry = fminf(yi2, s_y2[j]);
                float ww = fmaxf(__fsub_rn(rx, lx), 0.0f);
                float hh = fmaxf(__fsub_rn(ry, ly), 0.0f);
                float inter = __fmul_rn(ww, hh);
                float um = __fsub_rn(__fadd_rn(ai, s_area[j]), inter);
                bool hi = inter > __fmul_rn(IOU_HI, um);
                bool lo = inter < __fmul_rn(IOU_LO, um);
                bool sup = hi;
                if (!hi && !lo)
                    sup = (__fdiv_rn(inter, fmaxf(um, 1e-9f)) > 0.4f);
                if (sup) m |= (1u << jj);
            }
        } else if (j0 + 31 > i) {
            #pragma unroll 4
            for (int jj = 0; jj < 32; jj++) {
                int j = j0 + jj;
                if (j <= i) continue;
                float lx = fmaxf(xi1, s_x1[j]);
                float ly = fmaxf(yi1, s_y1[j]);
                float rx = fminf(xi2, s_x2[j]);
                float ry = fminf(yi2, s_y2[j]);
                float ww = fmaxf(__fsub_rn(rx, lx), 0.0f);
                float hh = fmaxf(__fsub_rn(ry, ly), 0.0f);
                float inter = __fmul_rn(ww, hh);
                float um = __fsub_rn(__fadd_rn(ai, s_area[j]), inter);
                bool hi = inter > __fmul_rn(IOU_HI, um);
                bool lo = inter < __fmul_rn(IOU_LO, um);
                bool sup = hi;
                if (!hi && !lo)
                    sup = (__fdiv_rn(inter, fmaxf(um, 1e-9f)) > 0.4f);
                if (sup) m |= (1u << jj);
            }
        }
        supb[(w << 10) + i] = m;
        if (m) s_rowf[i] = 1;
    }
    __syncthreads();
    for (int r = tid; r < KC; r += NT) {
        unsigned int bal = __ballot_sync(0xffffffffu, s_rowf[r] != 0);
        if (lane == 0)
            g_rowany[((b * SLICES + slice) << 5) + (r >> 5)] = bal;
    }
}

// ===================== kB: stage + diag-aware scan + output ==================
#define KB_SUP    0                       // 1024*33*4 = 135168
#define KB_X1     135168
#define KB_Y1     139264
#define KB_X2     143360
#define KB_Y2     147456
#define KB_SC     151552
#define KB_RAW    155648                  // u32[32]
#define KB_VALW   155776                  // u32[32]
#define KB_KEEPW  155904                  // u32[32]
#define KB_DIAG   156032                  // u32[32]
#define KB_TOTAL  156160

__global__ __launch_bounds__(NT, 1)
void kB_scan(float* __restrict__ out, int out_size)
{
    extern __shared__ unsigned char sm[];
    unsigned int*  s_sup   = (unsigned int*)(sm + KB_SUP);
    float*         s_x1    = (float*)(sm + KB_X1);
    float*         s_y1    = (float*)(sm + KB_Y1);
    float*         s_x2    = (float*)(sm + KB_X2);
    float*         s_y2    = (float*)(sm + KB_Y2);
    float*         s_sc    = (float*)(sm + KB_SC);
    unsigned int*  s_raw   = (unsigned int*)(sm + KB_RAW);
    unsigned int*  s_validw= (unsigned int*)(sm + KB_VALW);
    unsigned int*  s_keepw = (unsigned int*)(sm + KB_KEEPW);
    unsigned int*  s_diagm = (unsigned int*)(sm + KB_DIAG);

    const int b    = blockIdx.x;
    const int tid  = threadIdx.x;
    const int lane = tid & 31;
    const unsigned FULL = 0xffffffffu;

    // ---- validity + rowany ----
    for (int t = tid; t < KC; t += NT) {
        size_t o = (size_t)b * KC + t;
        s_x1[t] = g_bx1[o]; s_y1[t] = g_by1[o];
        s_x2[t] = g_bx2[o]; s_y2[t] = g_by2[o];
        float sc = __uint_as_float((unsigned int)(g_keys[o] >> 32));
        s_sc[t] = sc;
        unsigned int bal = __ballot_sync(FULL, sc > 0.5f);
        if (lane == 0) s_validw[t >> 5] = bal;
    }
    if (tid < 32) {
        unsigned int ra = 0;
        #pragma unroll
        for (int sl = 0; sl < SLICES; sl++)
            ra |= g_rowany[((b * SLICES + sl) << 5) + tid];
        s_raw[tid] = ra;
    }
    __syncthreads();

    // ---- stage only rows that can be kept suppressors (valid & rowany) ----
    const unsigned int* supb = g_sup + (size_t)b * WORDS * KC;
    for (int t = tid; t < WORDS * KC; t += NT) {
        int w = t >> 10;
        int i = t & 1023;
        unsigned int need = (s_raw[i >> 5] & s_validw[i >> 5]) >> (i & 31);
        if (need & 1u)
            s_sup[i * PAD + w] = supb[t];
    }
    __syncthreads();

    // ---- diag mask: rows with nonzero diagonal word (staged rows only) ----
    for (int t = tid; t < KC; t += NT) {
        int w = t >> 5;   // warp-uniform (NT multiple of 32)
        unsigned int need = (s_raw[w] & s_validw[w]) >> (t & 31);
        bool dg = (need & 1u) && (s_sup[t * PAD + w] != 0u);
        unsigned int bal = __ballot_sync(FULL, dg);
        if (lane == 0) s_diagm[w] = bal;
    }
    __syncthreads();

    // ---- greedy scan: one warp, diag-only serial chain + batched applies ----
    if (tid < 32) {
        unsigned int remv = 0;   // lane holds removed-mask for column word `lane`
        for (int w = 0; w < 32; w++) {
            unsigned int rm_w = __shfl_sync(FULL, remv, w);
            unsigned int vw = s_validw[w];
            unsigned int ra = s_raw[w];
            unsigned int diag = s_diagm[w];
            unsigned int kw = 0;
            unsigned int remaining = vw & ra;     // suppressor candidates
            // intra-word resolution: serial LDS only for kept diag rows
            for (;;) {
                unsigned int scand = remaining & ~rm_w;
                if (!scand) break;
                unsigned int dcand = scand & diag;
                if (!dcand) { kw |= scand; break; }   // rest kept in bulk
                int d = __ffs(dcand) - 1;
                unsigned int below = scand & ((1u << d) - 1u);
                kw |= below | (1u << d);
                remaining &= ~(below | (1u << d));
                rm_w |= s_sup[((w << 5) + d) * PAD + w];  // broadcast LDS
            }
            kw |= vw & ~ra & ~rm_w;   // non-suppressors kept iff not removed
            if (lane == 0) s_keepw[w] = kw;
            // batch apply: kept suppressors of this word -> all columns
            unsigned int app = kw & ra;
            while (app) {
                int bit = __ffs(app) - 1;
                app &= app - 1u;
                remv |= s_sup[((w << 5) + bit) * PAD + lane];  // independent
            }
        }
    }
    __syncthreads();

    // ---- outputs: dets [B,KC,5], keep [B,KC] ----
    const bool write_keep = (out_size >= BB * KC * 6);
    for (int t = tid; t < KC; t += NT) {
        bool kept = (s_keepw[t >> 5] >> (t & 31)) & 1u;
        float kf = kept ? 1.0f : 0.0f;
        size_t base = ((size_t)b * KC + t) * 5;
        out[base + 0] = __fmul_rn(s_x1[t], kf);
        out[base + 1] = __fmul_rn(s_y1[t], kf);
        out[base + 2] = __fmul_rn(s_x2[t], kf);
        out[base + 3] = __fmul_rn(s_y2[t], kf);
        out[base + 4] = __fmul_rn(s_sc[t], kf);
        if (write_keep)
            out[(size_t)BB * KC * 5 + (size_t)b * KC + t] = kf;
    }
}

// ======================= launch ==============================================
extern "C" void kernel_launch(void* const* d_in, const int* in_sizes, int n_in,
                              void* d_out, int out_size)
{
    (void)in_sizes; (void)n_in;
    cudaFuncSetAttribute(kB_scan,
        cudaFuncAttributeMaxDynamicSharedMemorySize, KB_TOTAL);
    const float* locs   = (const float*)d_in[0];
    const float* confs  = (const float*)d_in[1];
    const float* priors = (const float*)d_in[2];
    float* out = (float*)d_out;

    k1_score<<<dim3(2, BB), NT>>>(confs);
    kA2_select<<<BB, NT>>>(locs, priors);
    kS_supmat<<<dim3(SLICES, BB), NT>>>();
    kB_scan<<<BB, NT, KB_TOTAL>>>(out, out_size);
}

// round 8
// speedup vs baseline: 1.0262x; 1.0232x over previous
#include <cuda_runtime.h>
#include <cstdint>

// Problem constants
#define NP 21504   // priors per image
#define KC 1024    // top-k
#define BB 64      // batch
#define NT 512     // threads per block
#define WORDS 32   // KC/32 mask words
#define CCAP 2048  // candidate buffer (>= KC + bin slack)
#define PAD 33
#define SLICES 4   // supmat blocks per image
#define WPS 8      // words per slice
#define NBIN 4096  // top-12-bit score histogram (score <= 1.0 -> digit <= 4064)

// ---------------- global scratch (device globals: no allocs) ----------------
__device__ unsigned long long g_keys[BB * KC];
__device__ float              g_bx1[BB * KC];
__device__ float              g_by1[BB * KC];
__device__ float              g_bx2[BB * KC];
__device__ float              g_by2[BB * KC];
__device__ float              g_bar[BB * KC];
__device__ unsigned int       g_sup[BB * WORDS * KC];   // w-major, upper tri only
__device__ unsigned int       g_rowany[BB * SLICES * 32];

// ===================== kA: softmax + bin-select + sort + decode =============
// SMEM layout (bytes)
#define KA_SCORES 0        // 86016: float[NP]
#define KA_KEYS   86016    // 16384: u64[2048]
#define KA_HIST   102400   // 16384: u32[4096]
#define KA_WSUM   118784   // 64
#define KA_MISC   118848   // 16
#define KA_TOTAL  118912

__global__ __launch_bounds__(NT, 1)
void kA_select(const float* __restrict__ locs,
               const float* __restrict__ confs,
               const float* __restrict__ priors)
{
    extern __shared__ unsigned char sm[];
    float*              s_scores = (float*)(sm + KA_SCORES);
    unsigned long long* s_keys   = (unsigned long long*)(sm + KA_KEYS);
    unsigned int*       s_hist   = (unsigned int*)(sm + KA_HIST);
    unsigned int*       s_wsum   = (unsigned int*)(sm + KA_WSUM);
    int*                s_misc   = (int*)(sm + KA_MISC);

    const int b    = blockIdx.x;
    const int tid  = threadIdx.x;
    const int lane = tid & 31;
    const int wid  = tid >> 5;
    const unsigned FULL = 0xffffffffu;

    // ---- Phase 1: softmax (bit-identical to XLA) + 4096-bin histogram ----
    for (int i = tid; i < NBIN; i += NT) s_hist[i] = 0;
    if (tid == 0) s_misc[0] = 0;
    __syncthreads();
    const float* conf = confs + (size_t)b * NP * 2;
    for (int n = tid; n < NP; n += NT) {
        float2 c = __ldg((const float2*)(conf + 2 * n));
        // reference: m=max; e0=exp(x-m); e1=exp(y-m); s=e1/(e0+e1).
        // One exp is exp(0)=1 exactly -> single expf, identical rounding.
        float s;
        if (c.y >= c.x) {
            float e0 = expf(__fsub_rn(c.x, c.y));
            s = __fdiv_rn(1.0f, __fadd_rn(e0, 1.0f));
        } else {
            float e1 = expf(__fsub_rn(c.y, c.x));
            s = __fdiv_rn(e1, __fadd_rn(1.0f, e1));
        }
        s_scores[n] = s;
        unsigned int digit = __float_as_uint(s) >> 18;   // <= 4064 (s <= 1)
        unsigned int mmask = __match_any_sync(FULL, digit);
        if (lane == (__ffs(mmask) - 1))
            atomicAdd(&s_hist[digit], __popc(mmask));
    }
    __syncthreads();

    // ---- Phase 2: suffix scan over 4096 bins (8 bins/thread) ----
    {
        unsigned int v[8], S = 0;
        #pragma unroll
        for (int k = 0; k < 8; k++) { v[k] = s_hist[8 * tid + k]; S += v[k]; }
        unsigned int sfx = S;
        #pragma unroll
        for (int off = 1; off < 32; off <<= 1) {
            unsigned int u = __shfl_down_sync(FULL, sfx, off);
            if (lane + off < 32) sfx += u;
        }
        if (lane == 0) s_wsum[wid] = sfx;   // warp total
        __syncthreads();
        unsigned int cross = 0;
        for (int w2 = wid + 1; w2 < 16; w2++) cross += s_wsum[w2];
        unsigned int T_t = sfx + cross;     // suffix over threads >= tid
        unsigned int sb[9];
        sb[8] = T_t - S;
        #pragma unroll
        for (int k = 7; k >= 0; k--) sb[k] = sb[k + 1] + v[k];
        #pragma unroll
        for (int k = 0; k < 8; k++)
            if (sb[k] >= (unsigned)KC && sb[k + 1] < (unsigned)KC)
                s_misc[1] = 8 * tid + k;    // exactly one thread writes
    }
    for (int i = tid; i < CCAP; i += NT) s_keys[i] = 0ULL;
    __syncthreads();

    const unsigned int Tb = (unsigned int)s_misc[1] << 18;  // bin lower edge

    // ---- Phase 3: collect all scores >= Tb (superset of top-K) ----
    for (int n = tid; n < NP; n += NT) {
        unsigned int sbits = __float_as_uint(s_scores[n]);
        bool c = (sbits >= Tb);
        unsigned int bal = __ballot_sync(FULL, c);
        if (bal) {
            int leader = __ffs(bal) - 1;
            int base = 0;
            if (lane == leader) base = atomicAdd(&s_misc[0], __popc(bal));
            base = __shfl_sync(FULL, base, leader);
            if (c) {
                int p = base + __popc(bal & ((1u << lane) - 1u));
                if (p < CCAP)
                    s_keys[p] = ((unsigned long long)sbits << 32) |
                                (unsigned int)(~n);
            }
        }
    }
    __syncthreads();

    // ---- Phase 4: bitonic sort 2048 keys descending ----
    for (int k = 2; k <= CCAP; k <<= 1) {
        for (int j = k >> 1; j > 0; j >>= 1) {
            for (int i = tid; i < CCAP; i += NT) {
                int ixj = i ^ j;
                if (ixj > i) {
                    unsigned long long a = s_keys[i];
                    unsigned long long c = s_keys[ixj];
                    bool desc = ((i & k) == 0);
                    if (desc ? (a < c) : (a > c)) {
                        s_keys[i] = c; s_keys[ixj] = a;
                    }
                }
            }
            __syncthreads();
        }
    }

    // ---- Phase 5: decode boxes (no FMA contraction) + write scratch ----
    const float* loc = locs + (size_t)b * NP * 4;
    for (int t = tid; t < KC; t += NT) {
        unsigned long long key = s_keys[t];
        int idx = (int)(~(unsigned int)key);
        float4 l = __ldg((const float4*)(loc + 4 * (size_t)idx));
        float4 p = __ldg((const float4*)(priors + 4 * (size_t)idx));
        float cx = __fadd_rn(p.x, __fmul_rn(__fmul_rn(l.x, 0.1f), p.z));
        float cy = __fadd_rn(p.y, __fmul_rn(__fmul_rn(l.y, 0.1f), p.w));
        float w  = __fmul_rn(p.z, expf(__fmul_rn(l.z, 0.2f)));
        float h  = __fmul_rn(p.w, expf(__fmul_rn(l.w, 0.2f)));
        float x1 = __fsub_rn(cx, __fdiv_rn(w, 2.0f));
        float y1 = __fsub_rn(cy, __fdiv_rn(h, 2.0f));
        float x2 = __fadd_rn(x1, w);
        float y2 = __fadd_rn(y1, h);
        size_t o = (size_t)b * KC + t;
        g_bx1[o] = x1; g_by1[o] = y1; g_bx2[o] = x2; g_by2[o] = y2;
        float aw = fmaxf(__fsub_rn(x2, x1), 0.0f);
        float ah = fmaxf(__fsub_rn(y2, y1), 0.0f);
        g_bar[o] = __fmul_rn(aw, ah);
        g_keys[o] = key;
    }
}

// ===================== kS: suppression bitmatrix (4 slices/image) ============
#define IOU_HI 0.400008f
#define IOU_LO 0.399992f

__global__ __launch_bounds__(NT)
void kS_supmat()
{
    __shared__ float s_x1[KC], s_y1[KC], s_x2[KC], s_y2[KC], s_area[KC];
    __shared__ unsigned char s_rowf[KC];

    const int b     = blockIdx.y;
    const int slice = blockIdx.x;
    const int tid   = threadIdx.x;
    const int lane  = tid & 31;

    for (int t = tid; t < KC; t += NT) {
        size_t o = (size_t)b * KC + t;
        s_x1[t] = g_bx1[o]; s_y1[t] = g_by1[o];
        s_x2[t] = g_bx2[o]; s_y2[t] = g_by2[o];
        s_area[t] = g_bar[o];
        s_rowf[t] = 0;
    }
    __syncthreads();

    unsigned int* supb = g_sup + (size_t)b * WORDS * KC;
    for (int t = tid; t < WPS * KC; t += NT) {
        int w  = slice * WPS + (t >> 10);  // warp-uniform
        int i  = t & 1023;                 // consecutive across lanes
        int j0 = w << 5;
        int ibase = i & ~31;               // warp-uniform
        unsigned int m = 0;
        float xi1 = s_x1[i], yi1 = s_y1[i];
        float xi2 = s_x2[i], yi2 = s_y2[i];
        float ai  = s_area[i];
        if (j0 >= ibase + 32) {
            // full word: all j > i for every lane
            #pragma unroll 4
            for (int jj = 0; jj < 32; jj++) {
                int j = j0 + jj;
                float lx = fmaxf(xi1, s_x1[j]);
                float ly = fmaxf(yi1, s_y1[j]);
                float rx = fminf(xi2, s_x2[j]);
                float ry = fminf(yi2, s_y2[j]);
                float ww = fmaxf(__fsub_rn(rx, lx), 0.0f);
                float hh = fmaxf(__fsub_rn(ry, ly), 0.0f);
                float inter = __fmul_rn(ww, hh);
                float um = __fsub_rn(__fadd_rn(ai, s_area[j]), inter);
                bool hi = inter > __fmul_rn(IOU_HI, um);
                bool lo = inter < __fmul_rn(IOU_LO, um);
                bool sup = hi;
                if (!hi && !lo)
                    sup = (__fdiv_rn(inter, fmaxf(um, 1e-9f)) > 0.4f);
                if (sup) m |= (1u << jj);
            }
        } else if (j0 + 31 > i) {
            // diagonal word
            #pragma unroll 4
            for (int jj = 0; jj < 32; jj++) {
                int j = j0 + jj;
                if (j <= i) continue;
                float lx = fmaxf(xi1, s_x1[j]);
                float ly = fmaxf(yi1, s_y1[j]);
                float rx = fminf(xi2, s_x2[j]);
                float ry = fminf(yi2, s_y2[j]);
                float ww = fmaxf(__fsub_rn(rx, lx), 0.0f);
                float hh = fmaxf(__fsub_rn(ry, ly), 0.0f);
                float inter = __fmul_rn(ww, hh);
                float um = __fsub_rn(__fadd_rn(ai, s_area[j]), inter);
                bool hi = inter > __fmul_rn(IOU_HI, um);
                bool lo = inter < __fmul_rn(IOU_LO, um);
                bool sup = hi;
                if (!hi && !lo)
                    sup = (__fdiv_rn(inter, fmaxf(um, 1e-9f)) > 0.4f);
                if (sup) m |= (1u << jj);
            }
        }
        // store upper triangle only (w >= row's own word); lower never read
        if (w >= (i >> 5)) supb[(w << 10) + i] = m;
        if (m) s_rowf[i] = 1;              // benign race (writes of 1)
    }
    __syncthreads();
    for (int r = tid; r < KC; r += NT) {
        unsigned int bal = __ballot_sync(0xffffffffu, s_rowf[r] != 0);
        if (lane == 0)
            g_rowany[((b * SLICES + slice) << 5) + (r >> 5)] = bal;
    }
}

// ===================== kB: stage (upper tri) + scan + output =================
#define KB_SUP    0                       // 1024*33*4 = 135168
#define KB_X1     135168
#define KB_Y1     139264
#define KB_X2     143360
#define KB_Y2     147456
#define KB_SC     151552
#define KB_RAW    155648                  // u32[32]
#define KB_VALW   155776                  // u32[32]
#define KB_KEEPW  155904                  // u32[32]
#define KB_DIAG   156032                  // u32[32]
#define KB_TOTAL  156160

__global__ __launch_bounds__(NT, 1)
void kB_scan(float* __restrict__ out, int out_size)
{
    extern __shared__ unsigned char sm[];
    unsigned int*  s_sup   = (unsigned int*)(sm + KB_SUP);
    float*         s_x1    = (float*)(sm + KB_X1);
    float*         s_y1    = (float*)(sm + KB_Y1);
    float*         s_x2    = (float*)(sm + KB_X2);
    float*         s_y2    = (float*)(sm + KB_Y2);
    float*         s_sc    = (float*)(sm + KB_SC);
    unsigned int*  s_raw   = (unsigned int*)(sm + KB_RAW);
    unsigned int*  s_validw= (unsigned int*)(sm + KB_VALW);
    unsigned int*  s_keepw = (unsigned int*)(sm + KB_KEEPW);
    unsigned int*  s_diagm = (unsigned int*)(sm + KB_DIAG);

    const int b    = blockIdx.x;
    const int tid  = threadIdx.x;
    const int lane = tid & 31;
    const unsigned FULL = 0xffffffffu;

    // ---- validity + rowany ----
    for (int t = tid; t < KC; t += NT) {
        size_t o = (size_t)b * KC + t;
        s_x1[t] = g_bx1[o]; s_y1[t] = g_by1[o];
        s_x2[t] = g_bx2[o]; s_y2[t] = g_by2[o];
        float sc = __uint_as_float((unsigned int)(g_keys[o] >> 32));
        s_sc[t] = sc;
        unsigned int bal = __ballot_sync(FULL, sc > 0.5f);
        if (lane == 0) s_validw[t >> 5] = bal;
    }
    if (tid < 32) {
        unsigned int ra = 0;
        #pragma unroll
        for (int sl = 0; sl < SLICES; sl++)
            ra |= g_rowany[((b * SLICES + sl) << 5) + tid];
        s_raw[tid] = ra;
    }
    __syncthreads();

    // ---- stage only upper-triangle words of rows that can matter ----
    const unsigned int* supb = g_sup + (size_t)b * WORDS * KC;
    for (int t = tid; t < WORDS * KC; t += NT) {
        int w = t >> 10;
        int i = t & 1023;
        if (w < (i >> 5)) continue;        // strict lower: never written/read
        unsigned int need = (s_raw[i >> 5] & s_validw[i >> 5]) >> (i & 31);
        if (need & 1u)
            s_sup[i * PAD + w] = supb[t];
    }
    __syncthreads();

    // ---- diag mask: rows with nonzero diagonal word (staged rows only) ----
    for (int t = tid; t < KC; t += NT) {
        int w = t >> 5;   // warp-uniform
        unsigned int need = (s_raw[w] & s_validw[w]) >> (t & 31);
        bool dg = (need & 1u) && (s_sup[t * PAD + w] != 0u);
        unsigned int bal = __ballot_sync(FULL, dg);
        if (lane == 0) s_diagm[w] = bal;
    }
    __syncthreads();

    // ---- greedy scan: one warp, diag serial chain + batched applies ----
    if (tid < 32) {
        unsigned int remv = 0;   // lane holds removed-mask for column word lane
        for (int w = 0; w < 32; w++) {
            unsigned int rm_w = __shfl_sync(FULL, remv, w);
            unsigned int vw = s_validw[w];
            unsigned int ra = s_raw[w];
            unsigned int diag = s_diagm[w];
            unsigned int kw = 0;
            unsigned int remaining = vw & ra;
            for (;;) {
                unsigned int scand = remaining & ~rm_w;
                if (!scand) break;
                unsigned int dcand = scand & diag;
                if (!dcand) { kw |= scand; break; }
                int d = __ffs(dcand) - 1;
                unsigned int below = scand & ((1u << d) - 1u);
                kw |= below | (1u << d);
                remaining &= ~(below | (1u << d));
                rm_w |= s_sup[((w << 5) + d) * PAD + w];  // broadcast LDS
            }
            kw |= vw & ~ra & ~rm_w;
            if (lane == 0) s_keepw[w] = kw;
            // batch apply: kept suppressors -> columns >= w only (upper tri)
            unsigned int app = kw & ra;
            while (app) {
                int bit = __ffs(app) - 1;
                app &= app - 1u;
                if (lane >= w)
                    remv |= s_sup[((w << 5) + bit) * PAD + lane];
            }
        }
    }
    __syncthreads();

    // ---- outputs: dets [B,KC,5], keep [B,KC] ----
    const bool write_keep = (out_size >= BB * KC * 6);
    for (int t = tid; t < KC; t += NT) {
        bool kept = (s_keepw[t >> 5] >> (t & 31)) & 1u;
        float kf = kept ? 1.0f : 0.0f;
        size_t base = ((size_t)b * KC + t) * 5;
        out[base + 0] = __fmul_rn(s_x1[t], kf);
        out[base + 1] = __fmul_rn(s_y1[t], kf);
        out[base + 2] = __fmul_rn(s_x2[t], kf);
        out[base + 3] = __fmul_rn(s_y2[t], kf);
        out[base + 4] = __fmul_rn(s_sc[t], kf);
        if (write_keep)
            out[(size_t)BB * KC * 5 + (size_t)b * KC + t] = kf;
    }
}

// ======================= launch ==============================================
extern "C" void kernel_launch(void* const* d_in, const int* in_sizes, int n_in,
                              void* d_out, int out_size)
{
    (void)in_sizes; (void)n_in;
    cudaFuncSetAttribute(kA_select,
        cudaFuncAttributeMaxDynamicSharedMemorySize, KA_TOTAL);
    cudaFuncSetAttribute(kB_scan,
        cudaFuncAttributeMaxDynamicSharedMemorySize, KB_TOTAL);
    const float* locs   = (const float*)d_in[0];
    const float* confs  = (const float*)d_in[1];
    const float* priors = (const float*)d_in[2];
    float* out = (float*)d_out;

    kA_select<<<BB, NT, KA_TOTAL>>>(locs, confs, priors);
    kS_supmat<<<dim3(SLICES, BB), NT>>>();
    kB_scan<<<BB, NT, KB_TOTAL>>>(out, out_size);
}

// round 9
// speedup vs baseline: 1.1921x; 1.1616x over previous
#include <cuda_runtime.h>
#include <cstdint>

// Problem constants
#define NP 21504   // priors per image
#define KC 1024    // top-k
#define BB 64      // batch
#define NT 512     // threads per block
#define WORDS 32   // KC/32 mask words
#define CCAP 4096  // candidate buffer (>= KC + 2 bins slack)
#define PAD 33
#define SLICES 4   // supmat blocks per image
#define WPS 8      // words per slice
#define NBIN 8192  // 13-bit monotone-d histogram

// ---------------- global scratch (device globals: no allocs) ----------------
__device__ unsigned long long g_keys[BB * KC];
__device__ float              g_bx1[BB * KC];
__device__ float              g_by1[BB * KC];
__device__ float              g_bx2[BB * KC];
__device__ float              g_by2[BB * KC];
__device__ float              g_bar[BB * KC];
__device__ unsigned int       g_sup[BB * WORDS * KC];   // w-major, upper tri only
__device__ unsigned int       g_rowany[BB * SLICES * 32];

// monotone map: float bits -> unsigned preserving float ordering
__device__ __forceinline__ unsigned int fmap(float f) {
    unsigned int b = __float_as_uint(f);
    return ((int)b < 0) ? ~b : (b | 0x80000000u);
}

// ===================== kA: d-select + exact-s sort + decode ==================
// SMEM layout (bytes)
#define KA_D      0        // 86016: float[NP]  (d = fsub(cy,cx))
#define KA_KEYS   86016    // 32768: u64[4096]
#define KA_HIST   118784   // 32768: u32[8192]
#define KA_WSUM   151552   // 64
#define KA_MISC   151616   // 32
#define KA_TOTAL  151648

__global__ __launch_bounds__(NT, 1)
void kA_select(const float* __restrict__ locs,
               const float* __restrict__ confs,
               const float* __restrict__ priors)
{
    extern __shared__ unsigned char sm[];
    float*              s_d    = (float*)(sm + KA_D);
    unsigned long long* s_keys = (unsigned long long*)(sm + KA_KEYS);
    unsigned int*       s_hist = (unsigned int*)(sm + KA_HIST);
    unsigned int*       s_wsum = (unsigned int*)(sm + KA_WSUM);
    int*                s_misc = (int*)(sm + KA_MISC);

    const int b    = blockIdx.x;
    const int tid  = threadIdx.x;
    const int lane = tid & 31;
    const int wid  = tid >> 5;
    const unsigned FULL = 0xffffffffu;

    // ---- Phase 1: d = cy - cx (monotone proxy for score), 8192-bin hist ----
    for (int i = tid; i < NBIN; i += NT) s_hist[i] = 0;
    if (tid == 0) s_misc[0] = 0;
    __syncthreads();
    const float* conf = confs + (size_t)b * NP * 2;
    for (int n = tid; n < NP; n += NT) {
        float2 c = __ldg((const float2*)(conf + 2 * n));
        float d = __fsub_rn(c.y, c.x);
        s_d[n] = d;
        atomicAdd(&s_hist[fmap(d) >> 19], 1u);   // conflicts rare
    }
    __syncthreads();

    // ---- Phase 2: suffix scan over 8192 bins (16 bins/thread) ----
    {
        unsigned int v[16], S = 0;
        #pragma unroll
        for (int k = 0; k < 16; k++) { v[k] = s_hist[16 * tid + k]; S += v[k]; }
        unsigned int sfx = S;
        #pragma unroll
        for (int off = 1; off < 32; off <<= 1) {
            unsigned int u = __shfl_down_sync(FULL, sfx, off);
            if (lane + off < 32) sfx += u;
        }
        if (lane == 0) s_wsum[wid] = sfx;   // warp total
        __syncthreads();
        unsigned int cross = 0;
        for (int w2 = wid + 1; w2 < 16; w2++) cross += s_wsum[w2];
        unsigned int T_t = sfx + cross;     // suffix over threads >= tid
        unsigned int sb[17];
        sb[16] = T_t - S;
        #pragma unroll
        for (int k = 15; k >= 0; k--) sb[k] = sb[k + 1] + v[k];
        #pragma unroll
        for (int k = 0; k < 16; k++)
            if (sb[k] >= (unsigned)KC && sb[k + 1] < (unsigned)KC)
                s_misc[1] = 16 * tid + k;   // binK (exactly one writer)
    }
    for (int i = tid; i < CCAP; i += NT) s_keys[i] = 0ULL;
    __syncthreads();

    // collect cutoff: one full bin below binK (margin swallows any s-tie group)
    int binC = s_misc[1] - 1; if (binC < 0) binC = 0;
    const unsigned int Tu = (unsigned int)binC << 19;

    // ---- Phase 3: collect candidates (u >= Tu); exact s only for them ----
    for (int n = tid; n < NP; n += NT) {
        float d = s_d[n];
        bool c = (fmap(d) >= Tu);
        unsigned int bal = __ballot_sync(FULL, c);
        if (bal) {
            int leader = __ffs(bal) - 1;
            int base = 0;
            if (lane == leader) base = atomicAdd(&s_misc[0], __popc(bal));
            base = __shfl_sync(FULL, base, leader);
            if (c) {
                int p = base + __popc(bal & ((1u << lane) - 1u));
                if (p < CCAP) {
                    // exact reference softmax from rounded d (bit-identical):
                    float s;
                    if (d >= 0.0f) {
                        float e0 = expf(-d);            // = expf(fsub(cx,cy))
                        s = __fdiv_rn(1.0f, __fadd_rn(e0, 1.0f));
                    } else {
                        float e1 = expf(d);
                        s = __fdiv_rn(e1, __fadd_rn(1.0f, e1));
                    }
                    s_keys[p] = ((unsigned long long)__float_as_uint(s) << 32) |
                                (unsigned int)(~n);
                }
            }
        }
    }
    __syncthreads();

    // ---- Phase 4: bitonic sort (2048, or 4096 in rare overflow) ----
    const int SZ = (s_misc[0] <= 2048) ? 2048 : CCAP;
    for (int k = 2; k <= SZ; k <<= 1) {
        for (int j = k >> 1; j > 0; j >>= 1) {
            for (int i = tid; i < SZ; i += NT) {
                int ixj = i ^ j;
                if (ixj > i) {
                    unsigned long long a = s_keys[i];
                    unsigned long long c = s_keys[ixj];
                    bool desc = ((i & k) == 0);
                    if (desc ? (a < c) : (a > c)) {
                        s_keys[i] = c; s_keys[ixj] = a;
                    }
                }
            }
            __syncthreads();
        }
    }

    // ---- Phase 5: decode boxes (no FMA contraction) + write scratch ----
    const float* loc = locs + (size_t)b * NP * 4;
    for (int t = tid; t < KC; t += NT) {
        unsigned long long key = s_keys[t];
        int idx = (int)(~(unsigned int)key);
        float4 l = __ldg((const float4*)(loc + 4 * (size_t)idx));
        float4 p = __ldg((const float4*)(priors + 4 * (size_t)idx));
        float cx = __fadd_rn(p.x, __fmul_rn(__fmul_rn(l.x, 0.1f), p.z));
        float cy = __fadd_rn(p.y, __fmul_rn(__fmul_rn(l.y, 0.1f), p.w));
        float w  = __fmul_rn(p.z, expf(__fmul_rn(l.z, 0.2f)));
        float h  = __fmul_rn(p.w, expf(__fmul_rn(l.w, 0.2f)));
        float x1 = __fsub_rn(cx, __fdiv_rn(w, 2.0f));
        float y1 = __fsub_rn(cy, __fdiv_rn(h, 2.0f));
        float x2 = __fadd_rn(x1, w);
        float y2 = __fadd_rn(y1, h);
        size_t o = (size_t)b * KC + t;
        g_bx1[o] = x1; g_by1[o] = y1; g_bx2[o] = x2; g_by2[o] = y2;
        float aw = fmaxf(__fsub_rn(x2, x1), 0.0f);
        float ah = fmaxf(__fsub_rn(y2, y1), 0.0f);
        g_bar[o] = __fmul_rn(aw, ah);
        g_keys[o] = key;
    }
}

// ===================== kS: suppression bitmatrix (4 slices/image) ============
#define IOU_HI 0.400008f
#define IOU_LO 0.399992f

__global__ __launch_bounds__(NT)
void kS_supmat()
{
    __shared__ float s_x1[KC], s_y1[KC], s_x2[KC], s_y2[KC], s_area[KC];
    __shared__ unsigned char s_rowf[KC];

    const int b     = blockIdx.y;
    const int slice = blockIdx.x;
    const int tid   = threadIdx.x;
    const int lane  = tid & 31;

    for (int t = tid; t < KC; t += NT) {
        size_t o = (size_t)b * KC + t;
        s_x1[t] = g_bx1[o]; s_y1[t] = g_by1[o];
        s_x2[t] = g_bx2[o]; s_y2[t] = g_by2[o];
        s_area[t] = g_bar[o];
        s_rowf[t] = 0;
    }
    __syncthreads();

    unsigned int* supb = g_sup + (size_t)b * WORDS * KC;
    for (int t = tid; t < WPS * KC; t += NT) {
        int w  = slice * WPS + (t >> 10);  // warp-uniform
        int i  = t & 1023;                 // consecutive across lanes
        int j0 = w << 5;
        int ibase = i & ~31;               // warp-uniform
        unsigned int m = 0;
        float xi1 = s_x1[i], yi1 = s_y1[i];
        float xi2 = s_x2[i], yi2 = s_y2[i];
        float ai  = s_area[i];
        if (j0 >= ibase + 32) {
            #pragma unroll 4
            for (int jj = 0; jj < 32; jj++) {
                int j = j0 + jj;
                float lx = fmaxf(xi1, s_x1[j]);
                float ly = fmaxf(yi1, s_y1[j]);
                float rx = fminf(xi2, s_x2[j]);
                float ry = fminf(yi2, s_y2[j]);
                float ww = fmaxf(__fsub_rn(rx, lx), 0.0f);
                float hh = fmaxf(__fsub_rn(ry, ly), 0.0f);
                float inter = __fmul_rn(ww, hh);
                float um = __fsub_rn(__fadd_rn(ai, s_area[j]), inter);
                bool hi = inter > __fmul_rn(IOU_HI, um);
                bool lo = inter < __fmul_rn(IOU_LO, um);
                bool sup = hi;
                if (!hi && !lo)
                    sup = (__fdiv_rn(inter, fmaxf(um, 1e-9f)) > 0.4f);
                if (sup) m |= (1u << jj);
            }
        } else if (j0 + 31 > i) {
            #pragma unroll 4
            for (int jj = 0; jj < 32; jj++) {
                int j = j0 + jj;
                if (j <= i) continue;
                float lx = fmaxf(xi1, s_x1[j]);
                float ly = fmaxf(yi1, s_y1[j]);
                float rx = fminf(xi2, s_x2[j]);
                float ry = fminf(yi2, s_y2[j]);
                float ww = fmaxf(__fsub_rn(rx, lx), 0.0f);
                float hh = fmaxf(__fsub_rn(ry, ly), 0.0f);
                float inter = __fmul_rn(ww, hh);
                float um = __fsub_rn(__fadd_rn(ai, s_area[j]), inter);
                bool hi = inter > __fmul_rn(IOU_HI, um);
                bool lo = inter < __fmul_rn(IOU_LO, um);
                bool sup = hi;
                if (!hi && !lo)
                    sup = (__fdiv_rn(inter, fmaxf(um, 1e-9f)) > 0.4f);
                if (sup) m |= (1u << jj);
            }
        }
        if (w >= (i >> 5)) supb[(w << 10) + i] = m;   // upper tri only
        if (m) s_rowf[i] = 1;
    }
    __syncthreads();
    for (int r = tid; r < KC; r += NT) {
        unsigned int bal = __ballot_sync(0xffffffffu, s_rowf[r] != 0);
        if (lane == 0)
            g_rowany[((b * SLICES + slice) << 5) + (r >> 5)] = bal;
    }
}

// ===================== kB: uint4 stage + scan + output =======================
#define KB_SUP    0                       // 1024*33*4 = 135168
#define KB_X1     135168
#define KB_Y1     139264
#define KB_X2     143360
#define KB_Y2     147456
#define KB_SC     151552
#define KB_RAW    155648                  // u32[32]
#define KB_VALW   155776                  // u32[32]
#define KB_KEEPW  155904                  // u32[32]
#define KB_DIAG   156032                  // u32[32]
#define KB_TOTAL  156160

__global__ __launch_bounds__(NT, 1)
void kB_scan(float* __restrict__ out, int out_size)
{
    extern __shared__ unsigned char sm[];
    unsigned int*  s_sup   = (unsigned int*)(sm + KB_SUP);
    float*         s_x1    = (float*)(sm + KB_X1);
    float*         s_y1    = (float*)(sm + KB_Y1);
    float*         s_x2    = (float*)(sm + KB_X2);
    float*         s_y2    = (float*)(sm + KB_Y2);
    float*         s_sc    = (float*)(sm + KB_SC);
    unsigned int*  s_raw   = (unsigned int*)(sm + KB_RAW);
    unsigned int*  s_validw= (unsigned int*)(sm + KB_VALW);
    unsigned int*  s_keepw = (unsigned int*)(sm + KB_KEEPW);
    unsigned int*  s_diagm = (unsigned int*)(sm + KB_DIAG);

    const int b    = blockIdx.x;
    const int tid  = threadIdx.x;
    const int lane = tid & 31;
    const unsigned FULL = 0xffffffffu;

    // ---- stage sup matrix, uint4 (w-major contiguous in i), upper tri ----
    const unsigned int* supb = g_sup + (size_t)b * WORDS * KC;
    const uint4* sup4 = (const uint4*)supb;
    #pragma unroll 4
    for (int t = tid; t < (WORDS * KC) / 4; t += NT) {
        int w  = t >> 8;            // word
        int i4 = (t & 255) << 2;    // row group of 4 (same i>>5 for all 4)
        if (w < (i4 >> 5)) continue;
        uint4 v = sup4[t];
        int base = i4 * PAD + w;
        s_sup[base]           = v.x;
        s_sup[base + PAD]     = v.y;
        s_sup[base + 2 * PAD] = v.z;
        s_sup[base + 3 * PAD] = v.w;
    }

    // ---- validity + rowany + boxes ----
    for (int t = tid; t < KC; t += NT) {
        size_t o = (size_t)b * KC + t;
        s_x1[t] = g_bx1[o]; s_y1[t] = g_by1[o];
        s_x2[t] = g_bx2[o]; s_y2[t] = g_by2[o];
        float sc = __uint_as_float((unsigned int)(g_keys[o] >> 32));
        s_sc[t] = sc;
        unsigned int bal = __ballot_sync(FULL, sc > 0.5f);
        if (lane == 0) s_validw[t >> 5] = bal;
    }
    if (tid < 32) {
        unsigned int ra = 0;
        #pragma unroll
        for (int sl = 0; sl < SLICES; sl++)
            ra |= g_rowany[((b * SLICES + sl) << 5) + tid];
        s_raw[tid] = ra;
    }
    __syncthreads();

    // ---- diag mask: rows with nonzero diagonal word ----
    for (int t = tid; t < KC; t += NT) {
        int w = t >> 5;   // warp-uniform
        bool dg = (s_sup[t * PAD + w] != 0u);
        unsigned int bal = __ballot_sync(FULL, dg);
        if (lane == 0) s_diagm[w] = bal & s_raw[w] & s_validw[w];
    }
    __syncthreads();

    // ---- greedy scan: one warp, diag serial chain + batched applies ----
    if (tid < 32) {
        unsigned int remv = 0;   // lane holds removed-mask for column word lane
        for (int w = 0; w < 32; w++) {
            unsigned int rm_w = __shfl_sync(FULL, remv, w);
            unsigned int vw = s_validw[w];
            unsigned int ra = s_raw[w];
            unsigned int diag = s_diagm[w];
            unsigned int kw = 0;
            unsigned int remaining = vw & ra;
            for (;;) {
                unsigned int scand = remaining & ~rm_w;
                if (!scand) break;
                unsigned int dcand = scand & diag;
                if (!dcand) { kw |= scand; break; }
                int d = __ffs(dcand) - 1;
                unsigned int below = scand & ((1u << d) - 1u);
                kw |= below | (1u << d);
                remaining &= ~(below | (1u << d));
                rm_w |= s_sup[((w << 5) + d) * PAD + w];  // broadcast LDS
            }
            kw |= vw & ~ra & ~rm_w;
            if (lane == 0) s_keepw[w] = kw;
            // batch apply: kept suppressors -> columns >= w (upper tri)
            unsigned int app = kw & ra;
            while (app) {
                int bit = __ffs(app) - 1;
                app &= app - 1u;
                if (lane >= w)
                    remv |= s_sup[((w << 5) + bit) * PAD + lane];
            }
        }
    }
    __syncthreads();

    // ---- outputs: dets [B,KC,5], keep [B,KC] ----
    const bool write_keep = (out_size >= BB * KC * 6);
    for (int t = tid; t < KC; t += NT) {
        bool kept = (s_keepw[t >> 5] >> (t & 31)) & 1u;
        float kf = kept ? 1.0f : 0.0f;
        size_t base = ((size_t)b * KC + t) * 5;
        out[base + 0] = __fmul_rn(s_x1[t], kf);
        out[base + 1] = __fmul_rn(s_y1[t], kf);
        out[base + 2] = __fmul_rn(s_x2[t], kf);
        out[base + 3] = __fmul_rn(s_y2[t], kf);
        out[base + 4] = __fmul_rn(s_sc[t], kf);
        if (write_keep)
            out[(size_t)BB * KC * 5 + (size_t)b * KC + t] = kf;
    }
}

// ======================= launch ==============================================
extern "C" void kernel_launch(void* const* d_in, const int* in_sizes, int n_in,
                              void* d_out, int out_size)
{
    (void)in_sizes; (void)n_in;
    cudaFuncSetAttribute(kA_select,
        cudaFuncAttributeMaxDynamicSharedMemorySize, KA_TOTAL);
    cudaFuncSetAttribute(kB_scan,
        cudaFuncAttributeMaxDynamicSharedMemorySize, KB_TOTAL);
    const float* locs   = (const float*)d_in[0];
    const float* confs  = (const float*)d_in[1];
    const float* priors = (const float*)d_in[2];
    float* out = (float*)d_out;

    kA_select<<<BB, NT, KA_TOTAL>>>(locs, confs, priors);
    kS_supmat<<<dim3(SLICES, BB), NT>>>();
    kB_scan<<<BB, NT, KB_TOTAL>>>(out, out_size);
}

// round 10
// speedup vs baseline: 1.2368x; 1.0375x over previous
#include <cuda_runtime.h>
#include <cstdint>

// Problem constants
#define NP 21504   // priors per image
#define HALF 10752 // NP/2
#define KC 1024    // top-k
#define BB 64      // batch
#define NT 512     // threads per block
#define NTA 1024   // threads for kA2
#define WORDS 32   // KC/32 mask words
#define CCAP 4096  // candidate buffer
#define PAD 33
#define SLICES 4   // supmat blocks per image
#define WPS 8      // words per slice
#define NBIN 8192  // 13-bit monotone-d histogram

// ---------------- global scratch (device globals: no allocs) ----------------
__device__ unsigned int       g_hist[BB * 2 * NBIN];   // 4 MB
__device__ unsigned long long g_keys[BB * KC];
__device__ float              g_bx1[BB * KC];
__device__ float              g_by1[BB * KC];
__device__ float              g_bx2[BB * KC];
__device__ float              g_by2[BB * KC];
__device__ float              g_bar[BB * KC];
__device__ unsigned int       g_sup[BB * WORDS * KC];  // w-major, upper tri only
__device__ unsigned int       g_rowany[BB * SLICES * 32];

// monotone map: float bits -> unsigned preserving float ordering
__device__ __forceinline__ unsigned int fmap(float f) {
    unsigned int b = __float_as_uint(f);
    return ((int)b < 0) ? ~b : (b | 0x80000000u);
}

// ===================== kH: d histogram (128 blocks, whole chip) ==============
__global__ __launch_bounds__(NT)
void kH_hist(const float* __restrict__ confs)
{
    __shared__ unsigned int s_hist[NBIN];
    const int b    = blockIdx.y;
    const int half = blockIdx.x;
    const int tid  = threadIdx.x;

    for (int i = tid; i < NBIN; i += NT) s_hist[i] = 0;
    __syncthreads();

    const float* conf = confs + (size_t)b * NP * 2;
    const int n0 = half * HALF;
    for (int n = n0 + tid; n < n0 + HALF; n += NT) {
        float2 c = __ldg((const float2*)(conf + 2 * n));
        float d = __fsub_rn(c.y, c.x);
        atomicAdd(&s_hist[fmap(d) >> 19], 1u);
    }
    __syncthreads();
    for (int i = tid; i < NBIN; i += NT)
        g_hist[((b * 2 + half) << 13) + i] = s_hist[i];
}

// ===================== kA2: threshold + collect + sort + decode ==============
// SMEM layout (bytes)
#define KA_KEYS   0        // 32768: u64[4096]
#define KA_HIST   32768    // 32768: u32[8192]
#define KA_WSUM   65536    // 128
#define KA_MISC   65664    // 32
#define KA_TOTAL  65696

__global__ __launch_bounds__(NTA, 1)
void kA2_select(const float* __restrict__ locs,
                const float* __restrict__ confs,
                const float* __restrict__ priors)
{
    extern __shared__ unsigned char sm[];
    unsigned long long* s_keys = (unsigned long long*)(sm + KA_KEYS);
    unsigned int*       s_hist = (unsigned int*)(sm + KA_HIST);
    unsigned int*       s_wsum = (unsigned int*)(sm + KA_WSUM);
    int*                s_misc = (int*)(sm + KA_MISC);

    const int b    = blockIdx.x;
    const int tid  = threadIdx.x;
    const int lane = tid & 31;
    const int wid  = tid >> 5;
    const unsigned FULL = 0xffffffffu;

    // ---- sum half-image histograms ----
    for (int i = tid; i < NBIN; i += NTA)
        s_hist[i] = g_hist[((b * 2) << 13) + i] +
                    g_hist[((b * 2 + 1) << 13) + i];
    if (tid == 0) s_misc[0] = 0;
    __syncthreads();

    // ---- suffix scan over 8192 bins (8 bins/thread, 32 warps) ----
    {
        unsigned int v[8], S = 0;
        #pragma unroll
        for (int k = 0; k < 8; k++) { v[k] = s_hist[8 * tid + k]; S += v[k]; }
        unsigned int sfx = S;
        #pragma unroll
        for (int off = 1; off < 32; off <<= 1) {
            unsigned int u = __shfl_down_sync(FULL, sfx, off);
            if (lane + off < 32) sfx += u;
        }
        if (lane == 0) s_wsum[wid] = sfx;   // warp total
        __syncthreads();
        unsigned int cross = 0;
        for (int w2 = wid + 1; w2 < 32; w2++) cross += s_wsum[w2];
        unsigned int T_t = sfx + cross;     // suffix over threads >= tid
        unsigned int sb[9];
        sb[8] = T_t - S;
        #pragma unroll
        for (int k = 7; k >= 0; k--) sb[k] = sb[k + 1] + v[k];
        #pragma unroll
        for (int k = 0; k < 8; k++)
            if (sb[k] >= (unsigned)KC && sb[k + 1] < (unsigned)KC)
                s_misc[1] = 8 * tid + k;    // binK (exactly one writer)
    }
    for (int i = tid; i < CCAP; i += NTA) s_keys[i] = 0ULL;
    __syncthreads();

    // collect cutoff: one bin below binK (margin swallows any s-tie plateau)
    int binC = s_misc[1] - 1; if (binC < 0) binC = 0;
    const unsigned int Tu = (unsigned int)binC << 19;

    // ---- collect candidates (recompute d from confs); exact s for them ----
    const float* conf = confs + (size_t)b * NP * 2;
    for (int n = tid; n < NP; n += NTA) {
        float2 c = __ldg((const float2*)(conf + 2 * n));
        float d = __fsub_rn(c.y, c.x);
        bool cc = (fmap(d) >= Tu);
        unsigned int bal = __ballot_sync(FULL, cc);
        if (bal) {
            int leader = __ffs(bal) - 1;
            int base = 0;
            if (lane == leader) base = atomicAdd(&s_misc[0], __popc(bal));
            base = __shfl_sync(FULL, base, leader);
            if (cc) {
                int p = base + __popc(bal & ((1u << lane) - 1u));
                if (p < CCAP) {
                    // exact reference softmax from rounded d (bit-identical):
                    float s;
                    if (d >= 0.0f) {
                        float e0 = expf(-d);           // = expf(fsub(cx,cy))
                        s = __fdiv_rn(1.0f, __fadd_rn(e0, 1.0f));
                    } else {
                        float e1 = expf(d);
                        s = __fdiv_rn(e1, __fadd_rn(1.0f, e1));
                    }
                    s_keys[p] = ((unsigned long long)__float_as_uint(s) << 32) |
                                (unsigned int)(~n);
                }
            }
        }
    }
    __syncthreads();

    // ---- bitonic sort (2048, or 4096 in rare overflow) ----
    const int SZ = (s_misc[0] <= 2048) ? 2048 : CCAP;
    for (int k = 2; k <= SZ; k <<= 1) {
        for (int j = k >> 1; j > 0; j >>= 1) {
            for (int i = tid; i < SZ; i += NTA) {
                int ixj = i ^ j;
                if (ixj > i) {
                    unsigned long long a = s_keys[i];
                    unsigned long long c = s_keys[ixj];
                    bool desc = ((i & k) == 0);
                    if (desc ? (a < c) : (a > c)) {
                        s_keys[i] = c; s_keys[ixj] = a;
                    }
                }
            }
            __syncthreads();
        }
    }

    // ---- decode boxes (no FMA contraction) + write scratch ----
    const float* loc = locs + (size_t)b * NP * 4;
    for (int t = tid; t < KC; t += NTA) {
        unsigned long long key = s_keys[t];
        int idx = (int)(~(unsigned int)key);
        float4 l = __ldg((const float4*)(loc + 4 * (size_t)idx));
        float4 p = __ldg((const float4*)(priors + 4 * (size_t)idx));
        float cx = __fadd_rn(p.x, __fmul_rn(__fmul_rn(l.x, 0.1f), p.z));
        float cy = __fadd_rn(p.y, __fmul_rn(__fmul_rn(l.y, 0.1f), p.w));
        float w  = __fmul_rn(p.z, expf(__fmul_rn(l.z, 0.2f)));
        float h  = __fmul_rn(p.w, expf(__fmul_rn(l.w, 0.2f)));
        float x1 = __fsub_rn(cx, __fdiv_rn(w, 2.0f));
        float y1 = __fsub_rn(cy, __fdiv_rn(h, 2.0f));
        float x2 = __fadd_rn(x1, w);
        float y2 = __fadd_rn(y1, h);
        size_t o = (size_t)b * KC + t;
        g_bx1[o] = x1; g_by1[o] = y1; g_bx2[o] = x2; g_by2[o] = y2;
        float aw = fmaxf(__fsub_rn(x2, x1), 0.0f);
        float ah = fmaxf(__fsub_rn(y2, y1), 0.0f);
        g_bar[o] = __fmul_rn(aw, ah);
        g_keys[o] = key;
    }
}

// ===================== kS: suppression bitmatrix (4 slices/image) ============
#define IOU_HI 0.400008f
#define IOU_LO 0.399992f

__global__ __launch_bounds__(NT)
void kS_supmat()
{
    __shared__ float s_x1[KC], s_y1[KC], s_x2[KC], s_y2[KC], s_area[KC];
    __shared__ unsigned char s_rowf[KC];

    const int b     = blockIdx.y;
    const int slice = blockIdx.x;
    const int tid   = threadIdx.x;
    const int lane  = tid & 31;

    for (int t = tid; t < KC; t += NT) {
        size_t o = (size_t)b * KC + t;
        s_x1[t] = g_bx1[o]; s_y1[t] = g_by1[o];
        s_x2[t] = g_bx2[o]; s_y2[t] = g_by2[o];
        s_area[t] = g_bar[o];
        s_rowf[t] = 0;
    }
    __syncthreads();

    unsigned int* supb = g_sup + (size_t)b * WORDS * KC;
    for (int t = tid; t < WPS * KC; t += NT) {
        int w  = slice * WPS + (t >> 10);  // warp-uniform
        int i  = t & 1023;                 // consecutive across lanes
        int j0 = w << 5;
        int ibase = i & ~31;               // warp-uniform
        unsigned int m = 0;
        float xi1 = s_x1[i], yi1 = s_y1[i];
        float xi2 = s_x2[i], yi2 = s_y2[i];
        float ai  = s_area[i];
        if (j0 >= ibase + 32) {
            #pragma unroll 4
            for (int jj = 0; jj < 32; jj++) {
                int j = j0 + jj;
                float lx = fmaxf(xi1, s_x1[j]);
                float ly = fmaxf(yi1, s_y1[j]);
                float rx = fminf(xi2, s_x2[j]);
                float ry = fminf(yi2, s_y2[j]);
                float ww = fmaxf(__fsub_rn(rx, lx), 0.0f);
                float hh = fmaxf(__fsub_rn(ry, ly), 0.0f);
                float inter = __fmul_rn(ww, hh);
                float um = __fsub_rn(__fadd_rn(ai, s_area[j]), inter);
                bool hi = inter > __fmul_rn(IOU_HI, um);
                bool lo = inter < __fmul_rn(IOU_LO, um);
                bool sup = hi;
                if (!hi && !lo)
                    sup = (__fdiv_rn(inter, fmaxf(um, 1e-9f)) > 0.4f);
                if (sup) m |= (1u << jj);
            }
        } else if (j0 + 31 > i) {
            #pragma unroll 4
            for (int jj = 0; jj < 32; jj++) {
                int j = j0 + jj;
                if (j <= i) continue;
                float lx = fmaxf(xi1, s_x1[j]);
                float ly = fmaxf(yi1, s_y1[j]);
                float rx = fminf(xi2, s_x2[j]);
                float ry = fminf(yi2, s_y2[j]);
                float ww = fmaxf(__fsub_rn(rx, lx), 0.0f);
                float hh = fmaxf(__fsub_rn(ry, ly), 0.0f);
                float inter = __fmul_rn(ww, hh);
                float um = __fsub_rn(__fadd_rn(ai, s_area[j]), inter);
                bool hi = inter > __fmul_rn(IOU_HI, um);
                bool lo = inter < __fmul_rn(IOU_LO, um);
                bool sup = hi;
                if (!hi && !lo)
                    sup = (__fdiv_rn(inter, fmaxf(um, 1e-9f)) > 0.4f);
                if (sup) m |= (1u << jj);
            }
        }
        if (w >= (i >> 5)) supb[(w << 10) + i] = m;   // upper tri only
        if (m) s_rowf[i] = 1;
    }
    __syncthreads();
    for (int r = tid; r < KC; r += NT) {
        unsigned int bal = __ballot_sync(0xffffffffu, s_rowf[r] != 0);
        if (lane == 0)
            g_rowany[((b * SLICES + slice) << 5) + (r >> 5)] = bal;
    }
}

// ===================== kB: uint4 stage + scan + output =======================
#define KB_SUP    0                       // 1024*33*4 = 135168
#define KB_X1     135168
#define KB_Y1     139264
#define KB_X2     143360
#define KB_Y2     147456
#define KB_SC     151552
#define KB_RAW    155648                  // u32[32]
#define KB_VALW   155776                  // u32[32]
#define KB_KEEPW  155904                  // u32[32]
#define KB_DIAG   156032                  // u32[32]
#define KB_TOTAL  156160

__global__ __launch_bounds__(NT, 1)
void kB_scan(float* __restrict__ out, int out_size)
{
    extern __shared__ unsigned char sm[];
    unsigned int*  s_sup   = (unsigned int*)(sm + KB_SUP);
    float*         s_x1    = (float*)(sm + KB_X1);
    float*         s_y1    = (float*)(sm + KB_Y1);
    float*         s_x2    = (float*)(sm + KB_X2);
    float*         s_y2    = (float*)(sm + KB_Y2);
    float*         s_sc    = (float*)(sm + KB_SC);
    unsigned int*  s_raw   = (unsigned int*)(sm + KB_RAW);
    unsigned int*  s_validw= (unsigned int*)(sm + KB_VALW);
    unsigned int*  s_keepw = (unsigned int*)(sm + KB_KEEPW);
    unsigned int*  s_diagm = (unsigned int*)(sm + KB_DIAG);

    const int b    = blockIdx.x;
    const int tid  = threadIdx.x;
    const int lane = tid & 31;
    const unsigned FULL = 0xffffffffu;

    // ---- stage sup matrix, uint4 (w-major contiguous in i), upper tri ----
    const unsigned int* supb = g_sup + (size_t)b * WORDS * KC;
    const uint4* sup4 = (const uint4*)supb;
    #pragma unroll 4
    for (int t = tid; t < (WORDS * KC) / 4; t += NT) {
        int w  = t >> 8;            // word
        int i4 = (t & 255) << 2;    // row group of 4 (same i>>5 for all 4)
        if (w < (i4 >> 5)) continue;
        uint4 v = sup4[t];
        int base = i4 * PAD + w;
        s_sup[base]           = v.x;
        s_sup[base + PAD]     = v.y;
        s_sup[base + 2 * PAD] = v.z;
        s_sup[base + 3 * PAD] = v.w;
    }

    // ---- validity + rowany + boxes ----
    for (int t = tid; t < KC; t += NT) {
        size_t o = (size_t)b * KC + t;
        s_x1[t] = g_bx1[o]; s_y1[t] = g_by1[o];
        s_x2[t] = g_bx2[o]; s_y2[t] = g_by2[o];
        float sc = __uint_as_float((unsigned int)(g_keys[o] >> 32));
        s_sc[t] = sc;
        unsigned int bal = __ballot_sync(FULL, sc > 0.5f);
        if (lane == 0) s_validw[t >> 5] = bal;
    }
    if (tid < 32) {
        unsigned int ra = 0;
        #pragma unroll
        for (int sl = 0; sl < SLICES; sl++)
            ra |= g_rowany[((b * SLICES + sl) << 5) + tid];
        s_raw[tid] = ra;
    }
    __syncthreads();

    // ---- diag mask: rows with nonzero diagonal word ----
    for (int t = tid; t < KC; t += NT) {
        int w = t >> 5;   // warp-uniform
        bool dg = (s_sup[t * PAD + w] != 0u);
        unsigned int bal = __ballot_sync(FULL, dg);
        if (lane == 0) s_diagm[w] = bal & s_raw[w] & s_validw[w];
    }
    __syncthreads();

    // ---- greedy scan: one warp, diag serial chain + batched applies ----
    if (tid < 32) {
        unsigned int remv = 0;   // lane holds removed-mask for column word lane
        for (int w = 0; w < 32; w++) {
            unsigned int rm_w = __shfl_sync(FULL, remv, w);
            unsigned int vw = s_validw[w];
            unsigned int ra = s_raw[w];
            unsigned int diag = s_diagm[w];
            unsigned int kw = 0;
            unsigned int remaining = vw & ra;
            for (;;) {
                unsigned int scand = remaining & ~rm_w;
                if (!scand) break;
                unsigned int dcand = scand & diag;
                if (!dcand) { kw |= scand; break; }
                int d = __ffs(dcand) - 1;
                unsigned int below = scand & ((1u << d) - 1u);
                kw |= below | (1u << d);
                remaining &= ~(below | (1u << d));
                rm_w |= s_sup[((w << 5) + d) * PAD + w];  // broadcast LDS
            }
            kw |= vw & ~ra & ~rm_w;
            if (lane == 0) s_keepw[w] = kw;
            // batch apply: kept suppressors -> columns >= w (upper tri)
            unsigned int app = kw & ra;
            while (app) {
                int bit = __ffs(app) - 1;
                app &= app - 1u;
                if (lane >= w)
                    remv |= s_sup[((w << 5) + bit) * PAD + lane];
            }
        }
    }
    __syncthreads();

    // ---- outputs: dets [B,KC,5], keep [B,KC] ----
    const bool write_keep = (out_size >= BB * KC * 6);
    for (int t = tid; t < KC; t += NT) {
        bool kept = (s_keepw[t >> 5] >> (t & 31)) & 1u;
        float kf = kept ? 1.0f : 0.0f;
        size_t base = ((size_t)b * KC + t) * 5;
        out[base + 0] = __fmul_rn(s_x1[t], kf);
        out[base + 1] = __fmul_rn(s_y1[t], kf);
        out[base + 2] = __fmul_rn(s_x2[t], kf);
        out[base + 3] = __fmul_rn(s_y2[t], kf);
        out[base + 4] = __fmul_rn(s_sc[t], kf);
        if (write_keep)
            out[(size_t)BB * KC * 5 + (size_t)b * KC + t] = kf;
    }
}

// ======================= launch ==============================================
extern "C" void kernel_launch(void* const* d_in, const int* in_sizes, int n_in,
                              void* d_out, int out_size)
{
    (void)in_sizes; (void)n_in;
    cudaFuncSetAttribute(kA2_select,
        cudaFuncAttributeMaxDynamicSharedMemorySize, KA_TOTAL);
    cudaFuncSetAttribute(kB_scan,
        cudaFuncAttributeMaxDynamicSharedMemorySize, KB_TOTAL);
    const float* locs   = (const float*)d_in[0];
    const float* confs  = (const float*)d_in[1];
    const float* priors = (const float*)d_in[2];
    float* out = (float*)d_out;

    kH_hist<<<dim3(2, BB), NT>>>(confs);
    kA2_select<<<BB, NTA, KA_TOTAL>>>(locs, confs, priors);
    kS_supmat<<<dim3(SLICES, BB), NT>>>();
    kB_scan<<<BB, NT, KB_TOTAL>>>(out, out_size);
}

// round 11
// speedup vs baseline: 1.3263x; 1.0723x over previous
#include <cuda_runtime.h>
#include <cstdint>

// Problem constants
#define NP 21504   // priors per image
#define HALF 10752 // NP/2
#define KC 1024    // top-k
#define BB 64      // batch
#define NT 512     // threads per block
#define NTA 1024   // threads for kA2
#define WORDS 32   // KC/32 mask words
#define CCAP 4096  // candidate buffer
#define PAD 33
#define SLICES 8   // supmat blocks per image
#define WPS 4      // words per slice
#define NBIN 8192  // 13-bit monotone-d histogram

// ---------------- global scratch (device globals: no allocs) ----------------
__device__ unsigned int       g_hist[BB * 2 * NBIN];   // 4 MB
__device__ unsigned long long g_keys[BB * KC];
__device__ float4             g_box[BB * KC];          // x1,y1,x2,y2
__device__ float              g_bar[BB * KC];
__device__ unsigned int       g_sup[BB * WORDS * KC];  // w-major, upper tri only
__device__ unsigned int       g_rowany[BB * SLICES * 32];

// monotone map: float bits -> unsigned preserving float ordering
__device__ __forceinline__ unsigned int fmap(float f) {
    unsigned int b = __float_as_uint(f);
    return ((int)b < 0) ? ~b : (b | 0x80000000u);
}

// ===================== kH: d histogram (128 blocks, whole chip) ==============
__global__ __launch_bounds__(NT)
void kH_hist(const float* __restrict__ confs)
{
    __shared__ unsigned int s_hist[NBIN];
    const int b    = blockIdx.y;
    const int half = blockIdx.x;
    const int tid  = threadIdx.x;

    for (int i = tid; i < NBIN; i += NT) s_hist[i] = 0;
    __syncthreads();

    const float* conf = confs + (size_t)b * NP * 2;
    const int n0 = half * HALF;
    for (int n = n0 + tid; n < n0 + HALF; n += NT) {
        float2 c = __ldg((const float2*)(conf + 2 * n));
        float d = __fsub_rn(c.y, c.x);
        atomicAdd(&s_hist[fmap(d) >> 19], 1u);
    }
    __syncthreads();
    for (int i = tid; i < NBIN; i += NT)
        g_hist[((b * 2 + half) << 13) + i] = s_hist[i];
}

// ===================== kA2: threshold + collect + sort + decode ==============
// SMEM layout (bytes)
#define KA_KEYS   0        // 32768: u64[4096]
#define KA_HIST   32768    // 32768: u32[8192]
#define KA_WSUM   65536    // 128
#define KA_MISC   65664    // 32
#define KA_TOTAL  65696

__global__ __launch_bounds__(NTA, 1)
void kA2_select(const float* __restrict__ locs,
                const float* __restrict__ confs,
                const float* __restrict__ priors)
{
    extern __shared__ unsigned char sm[];
    unsigned long long* s_keys = (unsigned long long*)(sm + KA_KEYS);
    unsigned int*       s_hist = (unsigned int*)(sm + KA_HIST);
    unsigned int*       s_wsum = (unsigned int*)(sm + KA_WSUM);
    int*                s_misc = (int*)(sm + KA_MISC);

    const int b    = blockIdx.x;
    const int tid  = threadIdx.x;
    const int lane = tid & 31;
    const int wid  = tid >> 5;
    const unsigned FULL = 0xffffffffu;

    // ---- sum half-image histograms ----
    for (int i = tid; i < NBIN; i += NTA)
        s_hist[i] = g_hist[((b * 2) << 13) + i] +
                    g_hist[((b * 2 + 1) << 13) + i];
    if (tid == 0) s_misc[0] = 0;
    __syncthreads();

    // ---- suffix scan over 8192 bins (8 bins/thread, 32 warps) ----
    {
        unsigned int v[8], S = 0;
        #pragma unroll
        for (int k = 0; k < 8; k++) { v[k] = s_hist[8 * tid + k]; S += v[k]; }
        unsigned int sfx = S;
        #pragma unroll
        for (int off = 1; off < 32; off <<= 1) {
            unsigned int u = __shfl_down_sync(FULL, sfx, off);
            if (lane + off < 32) sfx += u;
        }
        if (lane == 0) s_wsum[wid] = sfx;   // warp total
        __syncthreads();
        unsigned int cross = 0;
        for (int w2 = wid + 1; w2 < 32; w2++) cross += s_wsum[w2];
        unsigned int T_t = sfx + cross;     // suffix over threads >= tid
        unsigned int sb[9];
        sb[8] = T_t - S;
        #pragma unroll
        for (int k = 7; k >= 0; k--) sb[k] = sb[k + 1] + v[k];
        #pragma unroll
        for (int k = 0; k < 8; k++)
            if (sb[k] >= (unsigned)KC && sb[k + 1] < (unsigned)KC)
                s_misc[1] = 8 * tid + k;    // binK (exactly one writer)
    }
    for (int i = tid; i < CCAP; i += NTA) s_keys[i] = 0ULL;
    __syncthreads();

    // collect cutoff: one bin below binK (margin swallows any s-tie plateau)
    int binC = s_misc[1] - 1; if (binC < 0) binC = 0;
    const unsigned int Tu = (unsigned int)binC << 19;

    // ---- collect candidates (recompute d from confs); exact s for them ----
    const float* conf = confs + (size_t)b * NP * 2;
    for (int n = tid; n < NP; n += NTA) {
        float2 c = __ldg((const float2*)(conf + 2 * n));
        float d = __fsub_rn(c.y, c.x);
        bool cc = (fmap(d) >= Tu);
        unsigned int bal = __ballot_sync(FULL, cc);
        if (bal) {
            int leader = __ffs(bal) - 1;
            int base = 0;
            if (lane == leader) base = atomicAdd(&s_misc[0], __popc(bal));
            base = __shfl_sync(FULL, base, leader);
            if (cc) {
                int p = base + __popc(bal & ((1u << lane) - 1u));
                if (p < CCAP) {
                    // exact reference softmax from rounded d (bit-identical)
                    float s;
                    if (d >= 0.0f) {
                        float e0 = expf(-d);           // = expf(fsub(cx,cy))
                        s = __fdiv_rn(1.0f, __fadd_rn(e0, 1.0f));
                    } else {
                        float e1 = expf(d);
                        s = __fdiv_rn(e1, __fadd_rn(1.0f, e1));
                    }
                    s_keys[p] = ((unsigned long long)__float_as_uint(s) << 32) |
                                (unsigned int)(~n);
                }
            }
        }
    }
    __syncthreads();

    // ---- bitonic sort (2048, or 4096 in rare overflow) ----
    const int SZ = (s_misc[0] <= 2048) ? 2048 : CCAP;
    for (int k = 2; k <= SZ; k <<= 1) {
        for (int j = k >> 1; j > 0; j >>= 1) {
            for (int i = tid; i < SZ; i += NTA) {
                int ixj = i ^ j;
                if (ixj > i) {
                    unsigned long long a = s_keys[i];
                    unsigned long long c = s_keys[ixj];
                    bool desc = ((i & k) == 0);
                    if (desc ? (a < c) : (a > c)) {
                        s_keys[i] = c; s_keys[ixj] = a;
                    }
                }
            }
            __syncthreads();
        }
    }

    // ---- decode boxes (no FMA contraction) + write scratch ----
    const float* loc = locs + (size_t)b * NP * 4;
    for (int t = tid; t < KC; t += NTA) {
        unsigned long long key = s_keys[t];
        int idx = (int)(~(unsigned int)key);
        float4 l = __ldg((const float4*)(loc + 4 * (size_t)idx));
        float4 p = __ldg((const float4*)(priors + 4 * (size_t)idx));
        float cx = __fadd_rn(p.x, __fmul_rn(__fmul_rn(l.x, 0.1f), p.z));
        float cy = __fadd_rn(p.y, __fmul_rn(__fmul_rn(l.y, 0.1f), p.w));
        float w  = __fmul_rn(p.z, expf(__fmul_rn(l.z, 0.2f)));
        float h  = __fmul_rn(p.w, expf(__fmul_rn(l.w, 0.2f)));
        float x1 = __fsub_rn(cx, __fdiv_rn(w, 2.0f));
        float y1 = __fsub_rn(cy, __fdiv_rn(h, 2.0f));
        float x2 = __fadd_rn(x1, w);
        float y2 = __fadd_rn(y1, h);
        size_t o = (size_t)b * KC + t;
        g_box[o] = make_float4(x1, y1, x2, y2);
        float aw = fmaxf(__fsub_rn(x2, x1), 0.0f);
        float ah = fmaxf(__fsub_rn(y2, y1), 0.0f);
        g_bar[o] = __fmul_rn(aw, ah);
        g_keys[o] = key;
    }
}

// ===================== kS: suppression bitmatrix (8 slices/image) ============
// iou > 0.4  <=>  3.5*inter > ai+aj  (reals). Band constants give +-5.7e-5
// relative margin >> rounding skew; in-band -> exact reference computation.
#define C_SUP  3.4998f
#define C_NOT  3.5002f

__device__ __forceinline__ bool iou_sup(float4 bi, float ai,
                                        float4 bj, float aj)
{
    float lx = fmaxf(bi.x, bj.x);
    float ly = fmaxf(bi.y, bj.y);
    float rx = fminf(bi.z, bj.z);
    float ry = fminf(bi.w, bj.w);
    float ww = fmaxf(__fsub_rn(rx, lx), 0.0f);
    float hh = fmaxf(__fsub_rn(ry, ly), 0.0f);
    float inter = __fmul_rn(ww, hh);
    float P = __fadd_rn(ai, aj);
    bool sup  = __fmaf_rn(C_SUP, inter, -P) > 0.0f;   // definitely > 0.4
    bool nsup = __fmaf_rn(C_NOT, inter, -P) < 0.0f;   // definitely <= 0.4
    if (!sup && !nsup) {   // rare band: exact reference
        float um = __fsub_rn(P, inter);
        sup = (__fdiv_rn(inter, fmaxf(um, 1e-9f)) > 0.4f);
    }
    return sup;
}

__global__ __launch_bounds__(NT)
void kS_supmat()
{
    __shared__ float4 s_box[KC];
    __shared__ float  s_area[KC];
    __shared__ unsigned char s_rowf[KC];

    const int b     = blockIdx.y;
    const int slice = blockIdx.x;
    const int tid   = threadIdx.x;
    const int lane  = tid & 31;

    for (int t = tid; t < KC; t += NT) {
        size_t o = (size_t)b * KC + t;
        s_box[t] = g_box[o];
        s_area[t] = g_bar[o];
        s_rowf[t] = 0;
    }
    __syncthreads();

    unsigned int* supb = g_sup + (size_t)b * WORDS * KC;
    for (int t = tid; t < WPS * KC; t += NT) {
        int w  = slice * WPS + (t >> 10);  // warp-uniform
        int i  = t & 1023;                 // consecutive across lanes
        int j0 = w << 5;
        int ibase = i & ~31;               // warp-uniform
        unsigned int m = 0;
        float4 bi = s_box[i];
        float  ai = s_area[i];
        if (j0 >= ibase + 32) {
            // full word: all j > i for every lane
            #pragma unroll 4
            for (int jj = 0; jj < 32; jj++) {
                int j = j0 + jj;           // warp-uniform -> broadcast LDS
                if (iou_sup(bi, ai, s_box[j], s_area[j])) m |= (1u << jj);
            }
        } else if (j0 + 31 > i) {
            // diagonal word
            #pragma unroll 4
            for (int jj = 0; jj < 32; jj++) {
                int j = j0 + jj;
                if (j <= i) continue;
                if (iou_sup(bi, ai, s_box[j], s_area[j])) m |= (1u << jj);
            }
        }
        if (w >= (i >> 5)) supb[(w << 10) + i] = m;   // upper tri only
        if (m) s_rowf[i] = 1;              // benign race (writes of 1)
    }
    __syncthreads();
    for (int r = tid; r < KC; r += NT) {
        unsigned int bal = __ballot_sync(0xffffffffu, s_rowf[r] != 0);
        if (lane == 0)
            g_rowany[((b * SLICES + slice) << 5) + (r >> 5)] = bal;
    }
}

// ===================== kB: uint4 stage + scan + output =======================
#define KB_SUP    0                       // 1024*33*4 = 135168
#define KB_BOX    135168                  // float4[1024] = 16384
#define KB_SC     151552
#define KB_RAW    155648                  // u32[32]
#define KB_VALW   155776                  // u32[32]
#define KB_KEEPW  155904                  // u32[32]
#define KB_DIAG   156032                  // u32[32]
#define KB_TOTAL  156160

__global__ __launch_bounds__(NT, 1)
void kB_scan(float* __restrict__ out, int out_size)
{
    extern __shared__ unsigned char sm[];
    unsigned int*  s_sup   = (unsigned int*)(sm + KB_SUP);
    float4*        s_box   = (float4*)(sm + KB_BOX);
    float*         s_sc    = (float*)(sm + KB_SC);
    unsigned int*  s_raw   = (unsigned int*)(sm + KB_RAW);
    unsigned int*  s_validw= (unsigned int*)(sm + KB_VALW);
    unsigned int*  s_keepw = (unsigned int*)(sm + KB_KEEPW);
    unsigned int*  s_diagm = (unsigned int*)(sm + KB_DIAG);

    const int b    = blockIdx.x;
    const int tid  = threadIdx.x;
    const int lane = tid & 31;
    const unsigned FULL = 0xffffffffu;

    // ---- stage sup matrix, uint4 (w-major contiguous in i), upper tri ----
    const unsigned int* supb = g_sup + (size_t)b * WORDS * KC;
    const uint4* sup4 = (const uint4*)supb;
    #pragma unroll 4
    for (int t = tid; t < (WORDS * KC) / 4; t += NT) {
        int w  = t >> 8;            // word
        int i4 = (t & 255) << 2;    // row group of 4 (same i>>5 for all 4)
        if (w < (i4 >> 5)) continue;
        uint4 v = sup4[t];
        int base = i4 * PAD + w;
        s_sup[base]           = v.x;
        s_sup[base + PAD]     = v.y;
        s_sup[base + 2 * PAD] = v.z;
        s_sup[base + 3 * PAD] = v.w;
    }

    // ---- validity + rowany + boxes ----
    for (int t = tid; t < KC; t += NT) {
        size_t o = (size_t)b * KC + t;
        s_box[t] = g_box[o];
        float sc = __uint_as_float((unsigned int)(g_keys[o] >> 32));
        s_sc[t] = sc;
        unsigned int bal = __ballot_sync(FULL, sc > 0.5f);
        if (lane == 0) s_validw[t >> 5] = bal;
    }
    if (tid < 32) {
        unsigned int ra = 0;
        #pragma unroll
        for (int sl = 0; sl < SLICES; sl++)
            ra |= g_rowany[((b * SLICES + sl) << 5) + tid];
        s_raw[tid] = ra;
    }
    __syncthreads();

    // ---- diag mask: rows with nonzero diagonal word ----
    for (int t = tid; t < KC; t += NT) {
        int w = t >> 5;   // warp-uniform
        bool dg = (s_sup[t * PAD + w] != 0u);
        unsigned int bal = __ballot_sync(FULL, dg);
        if (lane == 0) s_diagm[w] = bal & s_raw[w] & s_validw[w];
    }
    __syncthreads();

    // ---- greedy scan: one warp, diag serial chain + batched applies ----
    if (tid < 32) {
        unsigned int remv = 0;   // lane holds removed-mask for column word lane
        for (int w = 0; w < 32; w++) {
            unsigned int rm_w = __shfl_sync(FULL, remv, w);
            unsigned int vw = s_validw[w];
            unsigned int ra = s_raw[w];
            unsigned int diag = s_diagm[w];
            unsigned int kw = 0;
            unsigned int remaining = vw & ra;
            for (;;) {
                unsigned int scand = remaining & ~rm_w;
                if (!scand) break;
                unsigned int dcand = scand & diag;
                if (!dcand) { kw |= scand; break; }
                int d = __ffs(dcand) - 1;
                unsigned int below = scand & ((1u << d) - 1u);
                kw |= below | (1u << d);
                remaining &= ~(below | (1u << d));
                rm_w |= s_sup[((w << 5) + d) * PAD + w];  // broadcast LDS
            }
            kw |= vw & ~ra & ~rm_w;
            if (lane == 0) s_keepw[w] = kw;
            // batch apply: kept suppressors -> columns >= w (upper tri)
            unsigned int app = kw & ra;
            while (app) {
                int bit = __ffs(app) - 1;
                app &= app - 1u;
                if (lane >= w)
                    remv |= s_sup[((w << 5) + bit) * PAD + lane];
            }
        }
    }
    __syncthreads();

    // ---- outputs: dets [B,KC,5], keep [B,KC] ----
    const bool write_keep = (out_size >= BB * KC * 6);
    for (int t = tid; t < KC; t += NT) {
        bool kept = (s_keepw[t >> 5] >> (t & 31)) & 1u;
        float kf = kept ? 1.0f : 0.0f;
        float4 bx = s_box[t];
        size_t base = ((size_t)b * KC + t) * 5;
        out[base + 0] = __fmul_rn(bx.x, kf);
        out[base + 1] = __fmul_rn(bx.y, kf);
        out[base + 2] = __fmul_rn(bx.z, kf);
        out[base + 3] = __fmul_rn(bx.w, kf);
        out[base + 4] = __fmul_rn(s_sc[t], kf);
        if (write_keep)
            out[(size_t)BB * KC * 5 + (size_t)b * KC + t] = kf;
    }
}

// ======================= launch ==============================================
extern "C" void kernel_launch(void* const* d_in, const int* in_sizes, int n_in,
                              void* d_out, int out_size)
{
    (void)in_sizes; (void)n_in;
    cudaFuncSetAttribute(kA2_select,
        cudaFuncAttributeMaxDynamicSharedMemorySize, KA_TOTAL);
    cudaFuncSetAttribute(kB_scan,
        cudaFuncAttributeMaxDynamicSharedMemorySize, KB_TOTAL);
    const float* locs   = (const float*)d_in[0];
    const float* confs  = (const float*)d_in[1];
    const float* priors = (const float*)d_in[2];
    float* out = (float*)d_out;

    kH_hist<<<dim3(2, BB), NT>>>(confs);
    kA2_select<<<BB, NTA, KA_TOTAL>>>(locs, confs, priors);
    kS_supmat<<<dim3(SLICES, BB), NT>>>();
    kB_scan<<<BB, NT, KB_TOTAL>>>(out, out_size);
}

// round 12
// speedup vs baseline: 1.7293x; 1.3039x over previous
#include <cuda_runtime.h>
#include <cstdint>

// Problem constants
#define NP 21504   // priors per image
#define HALF 10752 // NP/2
#define KC 1024    // top-k
#define BB 64      // batch
#define NT 512     // threads per block
#define NTA 1024   // threads for kA2
#define WORDS 32   // KC/32 mask words
#define CCAP 4096  // candidate buffer
#define PAD 33
#define SLICES 8   // supmat blocks per image
#define WPS 4      // words per slice
#define NBIN 8192  // 13-bit monotone-d histogram

// ---------------- global scratch (device globals: no allocs) ----------------
__device__ unsigned int       g_hist[BB * 2 * NBIN];   // 4 MB
__device__ unsigned long long g_keys[BB * KC];
__device__ float4             g_box[BB * KC];          // x1,y1,x2,y2
__device__ float              g_bar[BB * KC];
__device__ unsigned int       g_sup[BB * WORDS * KC];  // w-major, upper tri only
__device__ unsigned int       g_rowany[BB * SLICES * 32];

// monotone map: float bits -> unsigned preserving float ordering
__device__ __forceinline__ unsigned int fmap(float f) {
    unsigned int b = __float_as_uint(f);
    return ((int)b < 0) ? ~b : (b | 0x80000000u);
}

// ===================== kH: d histogram (128 blocks, whole chip) ==============
__global__ __launch_bounds__(NT)
void kH_hist(const float* __restrict__ confs)
{
    __shared__ unsigned int s_hist[NBIN];
    const int b    = blockIdx.y;
    const int half = blockIdx.x;
    const int tid  = threadIdx.x;

    for (int i = tid; i < NBIN; i += NT) s_hist[i] = 0;
    __syncthreads();

    const float* conf = confs + (size_t)b * NP * 2;
    const int n0 = half * HALF;
    for (int n = n0 + tid; n < n0 + HALF; n += NT) {
        float2 c = __ldg((const float2*)(conf + 2 * n));
        float d = __fsub_rn(c.y, c.x);
        atomicAdd(&s_hist[fmap(d) >> 19], 1u);
    }
    __syncthreads();
    for (int i = tid; i < NBIN; i += NT)
        g_hist[((b * 2 + half) << 13) + i] = s_hist[i];
}

// ===================== kA2: threshold + collect + sort + decode ==============
// SMEM layout (bytes)
#define KA_KEYS   0        // 32768: u64[4096]
#define KA_HIST   32768    // 32768: u32[8192]
#define KA_WSUM   65536    // 128
#define KA_MISC   65664    // 32
#define KA_TOTAL  65696

__global__ __launch_bounds__(NTA, 1)
void kA2_select(const float* __restrict__ locs,
                const float* __restrict__ confs,
                const float* __restrict__ priors)
{
    extern __shared__ unsigned char sm[];
    unsigned long long* s_keys = (unsigned long long*)(sm + KA_KEYS);
    unsigned int*       s_hist = (unsigned int*)(sm + KA_HIST);
    unsigned int*       s_wsum = (unsigned int*)(sm + KA_WSUM);
    int*                s_misc = (int*)(sm + KA_MISC);

    const int b    = blockIdx.x;
    const int tid  = threadIdx.x;
    const int lane = tid & 31;
    const int wid  = tid >> 5;
    const unsigned FULL = 0xffffffffu;

    // ---- sum half-image histograms ----
    for (int i = tid; i < NBIN; i += NTA)
        s_hist[i] = g_hist[((b * 2) << 13) + i] +
                    g_hist[((b * 2 + 1) << 13) + i];
    if (tid == 0) s_misc[0] = 0;
    __syncthreads();

    // ---- suffix scan over 8192 bins (8 bins/thread, 32 warps) ----
    {
        unsigned int v[8], S = 0;
        #pragma unroll
        for (int k = 0; k < 8; k++) { v[k] = s_hist[8 * tid + k]; S += v[k]; }
        unsigned int sfx = S;
        #pragma unroll
        for (int off = 1; off < 32; off <<= 1) {
            unsigned int u = __shfl_down_sync(FULL, sfx, off);
            if (lane + off < 32) sfx += u;
        }
        if (lane == 0) s_wsum[wid] = sfx;   // warp total
        __syncthreads();
        unsigned int cross = 0;
        for (int w2 = wid + 1; w2 < 32; w2++) cross += s_wsum[w2];
        unsigned int T_t = sfx + cross;     // suffix over threads >= tid
        unsigned int sb[9];
        sb[8] = T_t - S;
        #pragma unroll
        for (int k = 7; k >= 0; k--) sb[k] = sb[k + 1] + v[k];
        #pragma unroll
        for (int k = 0; k < 8; k++)
            if (sb[k] >= (unsigned)KC && sb[k + 1] < (unsigned)KC)
                s_misc[1] = 8 * tid + k;    // binK (exactly one writer)
    }
    for (int i = tid; i < CCAP; i += NTA) s_keys[i] = 0ULL;
    __syncthreads();

    // collect cutoff: one bin below binK (margin swallows any s-tie plateau)
    int binC = s_misc[1] - 1; if (binC < 0) binC = 0;
    const unsigned int Tu = (unsigned int)binC << 19;

    // ---- collect candidates (recompute d from confs); exact s for them ----
    const float* conf = confs + (size_t)b * NP * 2;
    for (int n = tid; n < NP; n += NTA) {
        float2 c = __ldg((const float2*)(conf + 2 * n));
        float d = __fsub_rn(c.y, c.x);
        bool cc = (fmap(d) >= Tu);
        unsigned int bal = __ballot_sync(FULL, cc);
        if (bal) {
            int leader = __ffs(bal) - 1;
            int base = 0;
            if (lane == leader) base = atomicAdd(&s_misc[0], __popc(bal));
            base = __shfl_sync(FULL, base, leader);
            if (cc) {
                int p = base + __popc(bal & ((1u << lane) - 1u));
                if (p < CCAP) {
                    // exact reference softmax from rounded d (bit-identical)
                    float s;
                    if (d >= 0.0f) {
                        float e0 = expf(-d);           // = expf(fsub(cx,cy))
                        s = __fdiv_rn(1.0f, __fadd_rn(e0, 1.0f));
                    } else {
                        float e1 = expf(d);
                        s = __fdiv_rn(e1, __fadd_rn(1.0f, e1));
                    }
                    s_keys[p] = ((unsigned long long)__float_as_uint(s) << 32) |
                                (unsigned int)(~n);
                }
            }
        }
    }
    __syncthreads();

    // ---- bitonic sort descending (hybrid warp/SMEM network) ----
    if (s_misc[0] <= 2048) {
        // warp g owns elems [64g, 64g+64); lane holds e0=64g+lane, e1=e0+32
        const int e0 = (wid << 6) + lane;
        const int e1 = e0 + 32;
        unsigned long long a = s_keys[e0], b2 = s_keys[e1];

        // k = 2..64: fully in-warp (no barriers)
        #pragma unroll
        for (int k = 2; k <= 64; k <<= 1) {
            if (k == 64) {    // j=32 phase: both slots in this thread
                bool desc = ((e0 & 64) == 0);
                if (desc ? (a < b2) : (a > b2)) {
                    unsigned long long t2 = a; a = b2; b2 = t2;
                }
            }
            #pragma unroll
            for (int j = (k == 64 ? 16 : (k >> 1)); j > 0; j >>= 1) {
                unsigned long long pa = __shfl_xor_sync(FULL, a, j);
                unsigned long long pb = __shfl_xor_sync(FULL, b2, j);
                bool km0 = (((e0 & j) == 0) == ((e0 & k) == 0));
                bool km1 = (((e1 & j) == 0) == ((e1 & k) == 0));
                a  = km0 ? (a  > pa ? a  : pa) : (a  < pa ? a  : pa);
                b2 = km1 ? (b2 > pb ? b2 : pb) : (b2 < pb ? b2 : pb);
            }
        }
        s_keys[e0] = a; s_keys[e1] = b2;
        __syncthreads();

        // k = 128..2048: SMEM steps for j>=64, then in-warp tail (j<=32)
        for (int k = 128; k <= 2048; k <<= 1) {
            for (int j = k >> 1; j >= 64; j >>= 1) {
                #pragma unroll
                for (int rep = 0; rep < 2; rep++) {
                    int i = tid + rep * NTA;
                    int ixj = i ^ j;
                    if (ixj > i) {
                        unsigned long long x = s_keys[i];
                        unsigned long long y = s_keys[ixj];
                        bool desc = ((i & k) == 0);
                        if (desc ? (x < y) : (x > y)) {
                            s_keys[i] = y; s_keys[ixj] = x;
                        }
                    }
                }
                __syncthreads();
            }
            a = s_keys[e0]; b2 = s_keys[e1];
            {   // j=32 phase (e0&k == e1&k for k>=128)
                bool desc = ((e0 & k) == 0);
                if (desc ? (a < b2) : (a > b2)) {
                    unsigned long long t2 = a; a = b2; b2 = t2;
                }
            }
            #pragma unroll
            for (int j = 16; j > 0; j >>= 1) {
                unsigned long long pa = __shfl_xor_sync(FULL, a, j);
                unsigned long long pb = __shfl_xor_sync(FULL, b2, j);
                bool km0 = (((e0 & j) == 0) == ((e0 & k) == 0));
                bool km1 = (((e1 & j) == 0) == ((e1 & k) == 0));
                a  = km0 ? (a  > pa ? a  : pa) : (a  < pa ? a  : pa);
                b2 = km1 ? (b2 > pb ? b2 : pb) : (b2 < pb ? b2 : pb);
            }
            s_keys[e0] = a; s_keys[e1] = b2;
            __syncthreads();
        }
    } else {
        // rare overflow: plain SMEM bitonic over CCAP
        for (int k = 2; k <= CCAP; k <<= 1) {
            for (int j = k >> 1; j > 0; j >>= 1) {
                for (int i = tid; i < CCAP; i += NTA) {
                    int ixj = i ^ j;
                    if (ixj > i) {
                        unsigned long long x = s_keys[i];
                        unsigned long long y = s_keys[ixj];
                        bool desc = ((i & k) == 0);
                        if (desc ? (x < y) : (x > y)) {
                            s_keys[i] = y; s_keys[ixj] = x;
                        }
                    }
                }
                __syncthreads();
            }
        }
    }

    // ---- decode boxes (no FMA contraction) + write scratch ----
    const float* loc = locs + (size_t)b * NP * 4;
    for (int t = tid; t < KC; t += NTA) {
        unsigned long long key = s_keys[t];
        int idx = (int)(~(unsigned int)key);
        float4 l = __ldg((const float4*)(loc + 4 * (size_t)idx));
        float4 p = __ldg((const float4*)(priors + 4 * (size_t)idx));
        float cx = __fadd_rn(p.x, __fmul_rn(__fmul_rn(l.x, 0.1f), p.z));
        float cy = __fadd_rn(p.y, __fmul_rn(__fmul_rn(l.y, 0.1f), p.w));
        float w  = __fmul_rn(p.z, expf(__fmul_rn(l.z, 0.2f)));
        float h  = __fmul_rn(p.w, expf(__fmul_rn(l.w, 0.2f)));
        float x1 = __fsub_rn(cx, __fdiv_rn(w, 2.0f));
        float y1 = __fsub_rn(cy, __fdiv_rn(h, 2.0f));
        float x2 = __fadd_rn(x1, w);
        float y2 = __fadd_rn(y1, h);
        size_t o = (size_t)b * KC + t;
        g_box[o] = make_float4(x1, y1, x2, y2);
        float aw = fmaxf(__fsub_rn(x2, x1), 0.0f);
        float ah = fmaxf(__fsub_rn(y2, y1), 0.0f);
        g_bar[o] = __fmul_rn(aw, ah);
        g_keys[o] = key;
    }
}

// ===================== kS: suppression bitmatrix (8 slices, interleaved) =====
// iou > 0.4  <=>  3.5*inter > ai+aj  (reals). Band constants give +-5.7e-5
// relative margin >> rounding skew; in-band -> exact reference computation.
#define C_SUP  3.4998f
#define C_NOT  3.5002f

__device__ __forceinline__ bool iou_sup(float4 bi, float ai,
                                        float4 bj, float aj)
{
    float lx = fmaxf(bi.x, bj.x);
    float ly = fmaxf(bi.y, bj.y);
    float rx = fminf(bi.z, bj.z);
    float ry = fminf(bi.w, bj.w);
    float ww = fmaxf(__fsub_rn(rx, lx), 0.0f);
    float hh = fmaxf(__fsub_rn(ry, ly), 0.0f);
    float inter = __fmul_rn(ww, hh);
    float P = __fadd_rn(ai, aj);
    bool sup  = __fmaf_rn(C_SUP, inter, -P) > 0.0f;   // definitely > 0.4
    bool nsup = __fmaf_rn(C_NOT, inter, -P) < 0.0f;   // definitely <= 0.4
    if (!sup && !nsup) {   // rare band: exact reference
        float um = __fsub_rn(P, inter);
        sup = (__fdiv_rn(inter, fmaxf(um, 1e-9f)) > 0.4f);
    }
    return sup;
}

__global__ __launch_bounds__(NT)
void kS_supmat()
{
    __shared__ float4 s_box[KC];
    __shared__ float  s_area[KC];
    __shared__ unsigned char s_rowf[KC];

    const int b     = blockIdx.y;
    const int slice = blockIdx.x;
    const int tid   = threadIdx.x;
    const int lane  = tid & 31;

    for (int t = tid; t < KC; t += NT) {
        size_t o = (size_t)b * KC + t;
        s_box[t] = g_box[o];
        s_area[t] = g_bar[o];
        s_rowf[t] = 0;
    }
    __syncthreads();

    unsigned int* supb = g_sup + (size_t)b * WORDS * KC;
    for (int t = tid; t < WPS * KC; t += NT) {
        int w  = slice + ((t >> 10) << 3);  // stride-8 interleave: balanced
        int i  = t & 1023;                  // consecutive across lanes
        int j0 = w << 5;
        int ibase = i & ~31;                // warp-uniform
        unsigned int m = 0;
        float4 bi = s_box[i];
        float  ai = s_area[i];
        if (j0 >= ibase + 32) {
            // full word: all j > i for every lane
            #pragma unroll 4
            for (int jj = 0; jj < 32; jj++) {
                int j = j0 + jj;            // warp-uniform -> broadcast LDS
                if (iou_sup(bi, ai, s_box[j], s_area[j])) m |= (1u << jj);
            }
        } else if (j0 + 31 > i) {
            // diagonal word
            #pragma unroll 4
            for (int jj = 0; jj < 32; jj++) {
                int j = j0 + jj;
                if (j <= i) continue;
                if (iou_sup(bi, ai, s_box[j], s_area[j])) m |= (1u << jj);
            }
        }
        if (w >= (i >> 5)) supb[(w << 10) + i] = m;   // upper tri only
        if (m) s_rowf[i] = 1;               // benign race (writes of 1)
    }
    __syncthreads();
    for (int r = tid; r < KC; r += NT) {
        unsigned int bal = __ballot_sync(0xffffffffu, s_rowf[r] != 0);
        if (lane == 0)
            g_rowany[((b * SLICES + slice) << 5) + (r >> 5)] = bal;
    }
}

// ===================== kB: uint4 stage + scan + output =======================
#define KB_SUP    0                       // 1024*33*4 = 135168
#define KB_BOX    135168                  // float4[1024] = 16384
#define KB_SC     151552
#define KB_RAW    155648                  // u32[32]
#define KB_VALW   155776                  // u32[32]
#define KB_KEEPW  155904                  // u32[32]
#define KB_DIAG   156032                  // u32[32]
#define KB_TOTAL  156160

__global__ __launch_bounds__(NT, 1)
void kB_scan(float* __restrict__ out, int out_size)
{
    extern __shared__ unsigned char sm[];
    unsigned int*  s_sup   = (unsigned int*)(sm + KB_SUP);
    float4*        s_box   = (float4*)(sm + KB_BOX);
    float*         s_sc    = (float*)(sm + KB_SC);
    unsigned int*  s_raw   = (unsigned int*)(sm + KB_RAW);
    unsigned int*  s_validw= (unsigned int*)(sm + KB_VALW);
    unsigned int*  s_keepw = (unsigned int*)(sm + KB_KEEPW);
    unsigned int*  s_diagm = (unsigned int*)(sm + KB_DIAG);

    const int b    = blockIdx.x;
    const int tid  = threadIdx.x;
    const int lane = tid & 31;
    const unsigned FULL = 0xffffffffu;

    // ---- stage sup matrix, uint4 (w-major contiguous in i), upper tri ----
    const unsigned int* supb = g_sup + (size_t)b * WORDS * KC;
    const uint4* sup4 = (const uint4*)supb;
    #pragma unroll 4
    for (int t = tid; t < (WORDS * KC) / 4; t += NT) {
        int w  = t >> 8;            // word
        int i4 = (t & 255) << 2;    // row group of 4 (same i>>5 for all 4)
        if (w < (i4 >> 5)) continue;
        uint4 v = sup4[t];
        int base = i4 * PAD + w;
        s_sup[base]           = v.x;
        s_sup[base + PAD]     = v.y;
        s_sup[base + 2 * PAD] = v.z;
        s_sup[base + 3 * PAD] = v.w;
    }

    // ---- validity + rowany + boxes ----
    for (int t = tid; t < KC; t += NT) {
        size_t o = (size_t)b * KC + t;
        s_box[t] = g_box[o];
        float sc = __uint_as_float((unsigned int)(g_keys[o] >> 32));
        s_sc[t] = sc;
        unsigned int bal = __ballot_sync(FULL, sc > 0.5f);
        if (lane == 0) s_validw[t >> 5] = bal;
    }
    if (tid < 32) {
        unsigned int ra = 0;
        #pragma unroll
        for (int sl = 0; sl < SLICES; sl++)
            ra |= g_rowany[((b * SLICES + sl) << 5) + tid];
        s_raw[tid] = ra;
    }
    __syncthreads();

    // ---- diag mask: rows with nonzero diagonal word ----
    for (int t = tid; t < KC; t += NT) {
        int w = t >> 5;   // warp-uniform
        bool dg = (s_sup[t * PAD + w] != 0u);
        unsigned int bal = __ballot_sync(FULL, dg);
        if (lane == 0) s_diagm[w] = bal & s_raw[w] & s_validw[w];
    }
    __syncthreads();

    // ---- greedy scan: one warp, diag serial chain + batched applies ----
    if (tid < 32) {
        unsigned int remv = 0;   // lane holds removed-mask for column word lane
        for (int w = 0; w < 32; w++) {
            unsigned int rm_w = __shfl_sync(FULL, remv, w);
            unsigned int vw = s_validw[w];
            unsigned int ra = s_raw[w];
            unsigned int diag = s_diagm[w];
            unsigned int kw = 0;
            unsigned int remaining = vw & ra;
            for (;;) {
                unsigned int scand = remaining & ~rm_w;
                if (!scand) break;
                unsigned int dcand = scand & diag;
                if (!dcand) { kw |= scand; break; }
                int d = __ffs(dcand) - 1;
                unsigned int below = scand & ((1u << d) - 1u);
                kw |= below | (1u << d);
                remaining &= ~(below | (1u << d));
                rm_w |= s_sup[((w << 5) + d) * PAD + w];  // broadcast LDS
            }
            kw |= vw & ~ra & ~rm_w;
            if (lane == 0) s_keepw[w] = kw;
            // batch apply: kept suppressors -> columns >= w (upper tri)
            unsigned int app = kw & ra;
            while (app) {
                int bit = __ffs(app) - 1;
                app &= app - 1u;
                if (lane >= w)
                    remv |= s_sup[((w << 5) + bit) * PAD + lane];
            }
        }
    }
    __syncthreads();

    // ---- outputs: dets [B,KC,5], keep [B,KC] ----
    const bool write_keep = (out_size >= BB * KC * 6);
    for (int t = tid; t < KC; t += NT) {
        bool kept = (s_keepw[t >> 5] >> (t & 31)) & 1u;
        float kf = kept ? 1.0f : 0.0f;
        float4 bx = s_box[t];
        size_t base = ((size_t)b * KC + t) * 5;
        out[base + 0] = __fmul_rn(bx.x, kf);
        out[base + 1] = __fmul_rn(bx.y, kf);
        out[base + 2] = __fmul_rn(bx.z, kf);
        out[base + 3] = __fmul_rn(bx.w, kf);
        out[base + 4] = __fmul_rn(s_sc[t], kf);
        if (write_keep)
            out[(size_t)BB * KC * 5 + (size_t)b * KC + t] = kf;
    }
}

// ======================= launch ==============================================
extern "C" void kernel_launch(void* const* d_in, const int* in_sizes, int n_in,
                              void* d_out, int out_size)
{
    (void)in_sizes; (void)n_in;
    cudaFuncSetAttribute(kA2_select,
        cudaFuncAttributeMaxDynamicSharedMemorySize, KA_TOTAL);
    cudaFuncSetAttribute(kB_scan,
        cudaFuncAttributeMaxDynamicSharedMemorySize, KB_TOTAL);
    const float* locs   = (const float*)d_in[0];
    const float* confs  = (const float*)d_in[1];
    const float* priors = (const float*)d_in[2];
    float* out = (float*)d_out;

    kH_hist<<<dim3(2, BB), NT>>>(confs);
    kA2_select<<<BB, NTA, KA_TOTAL>>>(locs, confs, priors);
    kS_supmat<<<dim3(SLICES, BB), NT>>>();
    kB_scan<<<BB, NT, KB_TOTAL>>>(out, out_size);
}

// round 13
// speedup vs baseline: 1.7311x; 1.0010x over previous
#include <cuda_runtime.h>
#include <cstdint>

// Problem constants
#define NP 21504   // priors per image
#define HALF 10752 // NP/2
#define KC 1024    // top-k
#define BB 64      // batch
#define NT 512     // threads per block
#define NTA 1024   // threads for kA2
#define WORDS 32   // KC/32 mask words
#define CCAP 4096  // candidate buffer
#define SLICES 8   // supmat blocks per image
#define WPS 4      // words per slice
#define NBIN 8192  // 13-bit monotone-d histogram
#define PLANE 1028 // kB SMEM plane stride (words): 16B-aligned, 4-way max conflict

// ---------------- global scratch (device globals: no allocs) ----------------
__device__ unsigned int       g_hist[BB * 2 * NBIN];   // 4 MB
__device__ unsigned long long g_keys[BB * KC];
__device__ float4             g_box[BB * KC];          // x1,y1,x2,y2
__device__ float              g_bar[BB * KC];
__device__ unsigned int       g_sup[BB * WORDS * KC];  // w-major, upper tri only
__device__ unsigned int       g_rowany[BB * SLICES * 32];

// monotone map: float bits -> unsigned preserving float ordering
__device__ __forceinline__ unsigned int fmap(float f) {
    unsigned int b = __float_as_uint(f);
    return ((int)b < 0) ? ~b : (b | 0x80000000u);
}

// ===================== kH: d histogram (128 blocks, whole chip) ==============
__global__ __launch_bounds__(NT)
void kH_hist(const float* __restrict__ confs)
{
    __shared__ unsigned int s_hist[NBIN];
    const int b    = blockIdx.y;
    const int half = blockIdx.x;
    const int tid  = threadIdx.x;

    for (int i = tid; i < NBIN; i += NT) s_hist[i] = 0;
    __syncthreads();

    const float* conf = confs + (size_t)b * NP * 2;
    const int n0 = half * HALF;
    for (int n = n0 + tid; n < n0 + HALF; n += NT) {
        float2 c = __ldg((const float2*)(conf + 2 * n));
        float d = __fsub_rn(c.y, c.x);
        atomicAdd(&s_hist[fmap(d) >> 19], 1u);
    }
    __syncthreads();
    for (int i = tid; i < NBIN; i += NT)
        g_hist[((b * 2 + half) << 13) + i] = s_hist[i];
}

// ===================== kA2: threshold + collect + sort + decode ==============
// SMEM layout (bytes)
#define KA_KEYS   0        // 32768: u64[4096]
#define KA_HIST   32768    // 32768: u32[8192]
#define KA_WSUM   65536    // 128
#define KA_MISC   65664    // 32
#define KA_TOTAL  65696

__global__ __launch_bounds__(NTA, 1)
void kA2_select(const float* __restrict__ locs,
                const float* __restrict__ confs,
                const float* __restrict__ priors)
{
    extern __shared__ unsigned char sm[];
    unsigned long long* s_keys = (unsigned long long*)(sm + KA_KEYS);
    unsigned int*       s_hist = (unsigned int*)(sm + KA_HIST);
    unsigned int*       s_wsum = (unsigned int*)(sm + KA_WSUM);
    int*                s_misc = (int*)(sm + KA_MISC);

    const int b    = blockIdx.x;
    const int tid  = threadIdx.x;
    const int lane = tid & 31;
    const int wid  = tid >> 5;
    const unsigned FULL = 0xffffffffu;

    // ---- sum half-image histograms ----
    for (int i = tid; i < NBIN; i += NTA)
        s_hist[i] = g_hist[((b * 2) << 13) + i] +
                    g_hist[((b * 2 + 1) << 13) + i];
    if (tid == 0) s_misc[0] = 0;
    __syncthreads();

    // ---- suffix scan over 8192 bins (8 bins/thread, 32 warps) ----
    {
        unsigned int v[8], S = 0;
        #pragma unroll
        for (int k = 0; k < 8; k++) { v[k] = s_hist[8 * tid + k]; S += v[k]; }
        unsigned int sfx = S;
        #pragma unroll
        for (int off = 1; off < 32; off <<= 1) {
            unsigned int u = __shfl_down_sync(FULL, sfx, off);
            if (lane + off < 32) sfx += u;
        }
        if (lane == 0) s_wsum[wid] = sfx;   // warp total
        __syncthreads();
        unsigned int cross = 0;
        for (int w2 = wid + 1; w2 < 32; w2++) cross += s_wsum[w2];
        unsigned int T_t = sfx + cross;     // suffix over threads >= tid
        unsigned int sb[9];
        sb[8] = T_t - S;
        #pragma unroll
        for (int k = 7; k >= 0; k--) sb[k] = sb[k + 1] + v[k];
        #pragma unroll
        for (int k = 0; k < 8; k++)
            if (sb[k] >= (unsigned)KC && sb[k + 1] < (unsigned)KC)
                s_misc[1] = 8 * tid + k;    // binK (exactly one writer)
    }
    for (int i = tid; i < CCAP; i += NTA) s_keys[i] = 0ULL;
    __syncthreads();

    // collect cutoff: one bin below binK (margin swallows any s-tie plateau)
    int binC = s_misc[1] - 1; if (binC < 0) binC = 0;
    const unsigned int Tu = (unsigned int)binC << 19;

    // ---- collect candidates (recompute d from confs); exact s for them ----
    const float* conf = confs + (size_t)b * NP * 2;
    for (int n = tid; n < NP; n += NTA) {
        float2 c = __ldg((const float2*)(conf + 2 * n));
        float d = __fsub_rn(c.y, c.x);
        bool cc = (fmap(d) >= Tu);
        unsigned int bal = __ballot_sync(FULL, cc);
        if (bal) {
            int leader = __ffs(bal) - 1;
            int base = 0;
            if (lane == leader) base = atomicAdd(&s_misc[0], __popc(bal));
            base = __shfl_sync(FULL, base, leader);
            if (cc) {
                int p = base + __popc(bal & ((1u << lane) - 1u));
                if (p < CCAP) {
                    // exact reference softmax from rounded d (bit-identical)
                    float s;
                    if (d >= 0.0f) {
                        float e0 = expf(-d);           // = expf(fsub(cx,cy))
                        s = __fdiv_rn(1.0f, __fadd_rn(e0, 1.0f));
                    } else {
                        float e1 = expf(d);
                        s = __fdiv_rn(e1, __fadd_rn(1.0f, e1));
                    }
                    s_keys[p] = ((unsigned long long)__float_as_uint(s) << 32) |
                                (unsigned int)(~n);
                }
            }
        }
    }
    __syncthreads();

    // ---- bitonic sort descending (hybrid warp/SMEM network) ----
    if (s_misc[0] <= 2048) {
        // warp g owns elems [64g, 64g+64); lane holds e0=64g+lane, e1=e0+32
        const int e0 = (wid << 6) + lane;
        const int e1 = e0 + 32;
        unsigned long long a = s_keys[e0], b2 = s_keys[e1];

        // k = 2..64: fully in-warp (no barriers)
        #pragma unroll
        for (int k = 2; k <= 64; k <<= 1) {
            if (k == 64) {    // j=32 phase: both slots in this thread
                bool desc = ((e0 & 64) == 0);
                if (desc ? (a < b2) : (a > b2)) {
                    unsigned long long t2 = a; a = b2; b2 = t2;
                }
            }
            #pragma unroll
            for (int j = (k == 64 ? 16 : (k >> 1)); j > 0; j >>= 1) {
                unsigned long long pa = __shfl_xor_sync(FULL, a, j);
                unsigned long long pb = __shfl_xor_sync(FULL, b2, j);
                bool km0 = (((e0 & j) == 0) == ((e0 & k) == 0));
                bool km1 = (((e1 & j) == 0) == ((e1 & k) == 0));
                a  = km0 ? (a  > pa ? a  : pa) : (a  < pa ? a  : pa);
                b2 = km1 ? (b2 > pb ? b2 : pb) : (b2 < pb ? b2 : pb);
            }
        }
        s_keys[e0] = a; s_keys[e1] = b2;
        __syncthreads();

        // k = 128..2048: SMEM steps for j>=64, then in-warp tail (j<=32)
        for (int k = 128; k <= 2048; k <<= 1) {
            for (int j = k >> 1; j >= 64; j >>= 1) {
                #pragma unroll
                for (int rep = 0; rep < 2; rep++) {
                    int i = tid + rep * NTA;
                    int ixj = i ^ j;
                    if (ixj > i) {
                        unsigned long long x = s_keys[i];
                        unsigned long long y = s_keys[ixj];
                        bool desc = ((i & k) == 0);
                        if (desc ? (x < y) : (x > y)) {
                            s_keys[i] = y; s_keys[ixj] = x;
                        }
                    }
                }
                __syncthreads();
            }
            a = s_keys[e0]; b2 = s_keys[e1];
            {   // j=32 phase (e0&k == e1&k for k>=128)
                bool desc = ((e0 & k) == 0);
                if (desc ? (a < b2) : (a > b2)) {
                    unsigned long long t2 = a; a = b2; b2 = t2;
                }
            }
            #pragma unroll
            for (int j = 16; j > 0; j >>= 1) {
                unsigned long long pa = __shfl_xor_sync(FULL, a, j);
                unsigned long long pb = __shfl_xor_sync(FULL, b2, j);
                bool km0 = (((e0 & j) == 0) == ((e0 & k) == 0));
                bool km1 = (((e1 & j) == 0) == ((e1 & k) == 0));
                a  = km0 ? (a  > pa ? a  : pa) : (a  < pa ? a  : pa);
                b2 = km1 ? (b2 > pb ? b2 : pb) : (b2 < pb ? b2 : pb);
            }
            s_keys[e0] = a; s_keys[e1] = b2;
            __syncthreads();
        }
    } else {
        // rare overflow: plain SMEM bitonic over CCAP
        for (int k = 2; k <= CCAP; k <<= 1) {
            for (int j = k >> 1; j > 0; j >>= 1) {
                for (int i = tid; i < CCAP; i += NTA) {
                    int ixj = i ^ j;
                    if (ixj > i) {
                        unsigned long long x = s_keys[i];
                        unsigned long long y = s_keys[ixj];
                        bool desc = ((i & k) == 0);
                        if (desc ? (x < y) : (x > y)) {
                            s_keys[i] = y; s_keys[ixj] = x;
                        }
                    }
                }
                __syncthreads();
            }
        }
    }

    // ---- decode boxes (no FMA contraction) + write scratch ----
    const float* loc = locs + (size_t)b * NP * 4;
    for (int t = tid; t < KC; t += NTA) {
        unsigned long long key = s_keys[t];
        int idx = (int)(~(unsigned int)key);
        float4 l = __ldg((const float4*)(loc + 4 * (size_t)idx));
        float4 p = __ldg((const float4*)(priors + 4 * (size_t)idx));
        float cx = __fadd_rn(p.x, __fmul_rn(__fmul_rn(l.x, 0.1f), p.z));
        float cy = __fadd_rn(p.y, __fmul_rn(__fmul_rn(l.y, 0.1f), p.w));
        float w  = __fmul_rn(p.z, expf(__fmul_rn(l.z, 0.2f)));
        float h  = __fmul_rn(p.w, expf(__fmul_rn(l.w, 0.2f)));
        float x1 = __fsub_rn(cx, __fdiv_rn(w, 2.0f));
        float y1 = __fsub_rn(cy, __fdiv_rn(h, 2.0f));
        float x2 = __fadd_rn(x1, w);
        float y2 = __fadd_rn(y1, h);
        size_t o = (size_t)b * KC + t;
        g_box[o] = make_float4(x1, y1, x2, y2);
        float aw = fmaxf(__fsub_rn(x2, x1), 0.0f);
        float ah = fmaxf(__fsub_rn(y2, y1), 0.0f);
        g_bar[o] = __fmul_rn(aw, ah);
        g_keys[o] = key;
    }
}

// ===================== kS: suppression bitmatrix (8 slices, interleaved) =====
// iou > 0.4  <=>  3.5*inter > ai+aj  (reals). Band constants give +-5.7e-5
// relative margin >> rounding skew; in-band -> exact reference computation.
#define C_SUP  3.4998f
#define C_NOT  3.5002f

__device__ __forceinline__ bool iou_sup(float4 bi, float ai,
                                        float4 bj, float aj)
{
    float lx = fmaxf(bi.x, bj.x);
    float ly = fmaxf(bi.y, bj.y);
    float rx = fminf(bi.z, bj.z);
    float ry = fminf(bi.w, bj.w);
    float ww = fmaxf(__fsub_rn(rx, lx), 0.0f);
    float hh = fmaxf(__fsub_rn(ry, ly), 0.0f);
    float inter = __fmul_rn(ww, hh);
    float P = __fadd_rn(ai, aj);
    bool sup  = __fmaf_rn(C_SUP, inter, -P) > 0.0f;   // definitely > 0.4
    bool nsup = __fmaf_rn(C_NOT, inter, -P) < 0.0f;   // definitely <= 0.4
    if (!sup && !nsup) {   // rare band: exact reference
        float um = __fsub_rn(P, inter);
        sup = (__fdiv_rn(inter, fmaxf(um, 1e-9f)) > 0.4f);
    }
    return sup;
}

__global__ __launch_bounds__(NT)
void kS_supmat()
{
    __shared__ float4 s_box[KC];
    __shared__ float  s_area[KC];
    __shared__ unsigned char s_rowf[KC];

    const int b     = blockIdx.y;
    const int slice = blockIdx.x;
    const int tid   = threadIdx.x;
    const int lane  = tid & 31;

    for (int t = tid; t < KC; t += NT) {
        size_t o = (size_t)b * KC + t;
        s_box[t] = g_box[o];
        s_area[t] = g_bar[o];
        s_rowf[t] = 0;
    }
    __syncthreads();

    unsigned int* supb = g_sup + (size_t)b * WORDS * KC;
    for (int t = tid; t < WPS * KC; t += NT) {
        int w  = slice + ((t >> 10) << 3);  // stride-8 interleave: balanced
        int i  = t & 1023;                  // consecutive across lanes
        int j0 = w << 5;
        int ibase = i & ~31;                // warp-uniform
        unsigned int m = 0;
        float4 bi = s_box[i];
        float  ai = s_area[i];
        if (j0 >= ibase + 32) {
            // full word: all j > i for every lane
            #pragma unroll 4
            for (int jj = 0; jj < 32; jj++) {
                int j = j0 + jj;            // warp-uniform -> broadcast LDS
                if (iou_sup(bi, ai, s_box[j], s_area[j])) m |= (1u << jj);
            }
        } else if (j0 + 31 > i) {
            // diagonal word
            #pragma unroll 4
            for (int jj = 0; jj < 32; jj++) {
                int j = j0 + jj;
                if (j <= i) continue;
                if (iou_sup(bi, ai, s_box[j], s_area[j])) m |= (1u << jj);
            }
        }
        if (w >= (i >> 5)) supb[(w << 10) + i] = m;   // upper tri only
        if (m) s_rowf[i] = 1;               // benign race (writes of 1)
    }
    __syncthreads();
    for (int r = tid; r < KC; r += NT) {
        unsigned int bal = __ballot_sync(0xffffffffu, s_rowf[r] != 0);
        if (lane == 0)
            g_rowany[((b * SLICES + slice) << 5) + (r >> 5)] = bal;
    }
}

// ===================== kB: vector stage (w-major planes) + scan + output =====
// SMEM: sup planes w-major, stride PLANE=1028 words (16B aligned -> STS.128;
// apply reads addr lane*PLANE+i -> bank (4*lane+i)&31 -> 4-way max conflict).
#define KB_SUP    0                       // 32*1028*4 = 131584
#define KB_BOX    131584                  // float4[1024] = 16384
#define KB_SC     147968                  // 4096
#define KB_RAW    152064                  // u32[32]
#define KB_VALW   152192                  // u32[32]
#define KB_KEEPW  152320                  // u32[32]
#define KB_DIAG   152448                  // u32[32]
#define KB_TOTAL  152576

__global__ __launch_bounds__(NT, 1)
void kB_scan(float* __restrict__ out, int out_size)
{
    extern __shared__ unsigned char sm[];
    unsigned int*  s_sup   = (unsigned int*)(sm + KB_SUP);
    float4*        s_box   = (float4*)(sm + KB_BOX);
    float*         s_sc    = (float*)(sm + KB_SC);
    unsigned int*  s_raw   = (unsigned int*)(sm + KB_RAW);
    unsigned int*  s_validw= (unsigned int*)(sm + KB_VALW);
    unsigned int*  s_keepw = (unsigned int*)(sm + KB_KEEPW);
    unsigned int*  s_diagm = (unsigned int*)(sm + KB_DIAG);

    const int b    = blockIdx.x;
    const int tid  = threadIdx.x;
    const int lane = tid & 31;
    const unsigned FULL = 0xffffffffu;

    // ---- stage sup matrix: LDG.128 -> STS.128 into w-major planes ----
    const unsigned int* supb = g_sup + (size_t)b * WORDS * KC;
    const uint4* sup4 = (const uint4*)supb;
    #pragma unroll 4
    for (int t = tid; t < (WORDS * KC) / 4; t += NT) {
        int w  = t >> 8;            // word plane
        int i4 = (t & 255) << 2;    // row group of 4 (same i>>5 for all 4)
        if (w < (i4 >> 5)) continue;   // strict lower tri: never read
        uint4 v = sup4[t];
        *(uint4*)(s_sup + w * PLANE + i4) = v;
    }

    // ---- validity + rowany + boxes ----
    for (int t = tid; t < KC; t += NT) {
        size_t o = (size_t)b * KC + t;
        s_box[t] = g_box[o];
        float sc = __uint_as_float((unsigned int)(g_keys[o] >> 32));
        s_sc[t] = sc;
        unsigned int bal = __ballot_sync(FULL, sc > 0.5f);
        if (lane == 0) s_validw[t >> 5] = bal;
    }
    if (tid < 32) {
        unsigned int ra = 0;
        #pragma unroll
        for (int sl = 0; sl < SLICES; sl++)
            ra |= g_rowany[((b * SLICES + sl) << 5) + tid];
        s_raw[tid] = ra;
    }
    __syncthreads();

    // ---- diag mask: rows with nonzero diagonal word ----
    for (int t = tid; t < KC; t += NT) {
        int w = t >> 5;   // warp-uniform
        bool dg = (s_sup[w * PLANE + t] != 0u);
        unsigned int bal = __ballot_sync(FULL, dg);
        if (lane == 0) s_diagm[w] = bal & s_raw[w] & s_validw[w];
    }
    __syncthreads();

    // ---- greedy scan: one warp, diag serial chain + batched applies ----
    if (tid < 32) {
        unsigned int remv = 0;   // lane holds removed-mask for column word lane
        for (int w = 0; w < 32; w++) {
            unsigned int rm_w = __shfl_sync(FULL, remv, w);
            unsigned int vw = s_validw[w];
            unsigned int ra = s_raw[w];
            unsigned int diag = s_diagm[w];
            unsigned int kw = 0;
            unsigned int remaining = vw & ra;
            for (;;) {
                unsigned int scand = remaining & ~rm_w;
                if (!scand) break;
                unsigned int dcand = scand & diag;
                if (!dcand) { kw |= scand; break; }
                int d = __ffs(dcand) - 1;
                unsigned int below = scand & ((1u << d) - 1u);
                kw |= below | (1u << d);
                remaining &= ~(below | (1u << d));
                rm_w |= s_sup[w * PLANE + (w << 5) + d];  // broadcast LDS
            }
            kw |= vw & ~ra & ~rm_w;
            if (lane == 0) s_keepw[w] = kw;
            // batch apply: kept suppressors -> columns >= w (upper tri)
            unsigned int app = kw & ra;
            while (app) {
                int bit = __ffs(app) - 1;
                app &= app - 1u;
                if (lane >= w)
                    remv |= s_sup[lane * PLANE + (w << 5) + bit];
            }
        }
    }
    __syncthreads();

    // ---- outputs: dets [B,KC,5], keep [B,KC] ----
    const bool write_keep = (out_size >= BB * KC * 6);
    for (int t = tid; t < KC; t += NT) {
        bool kept = (s_keepw[t >> 5] >> (t & 31)) & 1u;
        float kf = kept ? 1.0f : 0.0f;
        float4 bx = s_box[t];
        size_t base = ((size_t)b * KC + t) * 5;
        out[base + 0] = __fmul_rn(bx.x, kf);
        out[base + 1] = __fmul_rn(bx.y, kf);
        out[base + 2] = __fmul_rn(bx.z, kf);
        out[base + 3] = __fmul_rn(bx.w, kf);
        out[base + 4] = __fmul_rn(s_sc[t], kf);
        if (write_keep)
            out[(size_t)BB * KC * 5 + (size_t)b * KC + t] = kf;
    }
}

// ======================= launch ==============================================
extern "C" void kernel_launch(void* const* d_in, const int* in_sizes, int n_in,
                              void* d_out, int out_size)
{
    (void)in_sizes; (void)n_in;
    cudaFuncSetAttribute(kA2_select,
        cudaFuncAttributeMaxDynamicSharedMemorySize, KA_TOTAL);
    cudaFuncSetAttribute(kB_scan,
        cudaFuncAttributeMaxDynamicSharedMemorySize, KB_TOTAL);
    const float* locs   = (const float*)d_in[0];
    const float* confs  = (const float*)d_in[1];
    const float* priors = (const float*)d_in[2];
    float* out = (float*)d_out;

    kH_hist<<<dim3(2, BB), NT>>>(confs);
    kA2_select<<<BB, NTA, KA_TOTAL>>>(locs, confs, priors);
    kS_supmat<<<dim3(SLICES, BB), NT>>>();
    kB_scan<<<BB, NT, KB_TOTAL>>>(out, out_size);
}